// round 1
// baseline (speedup 1.0000x reference)
#include <cuda_runtime.h>
#include <cstdint>
#include <cstdio>

// ----------------------------------------------------------------------------
// Problem constants
// ----------------------------------------------------------------------------
constexpr int BB    = 8;
constexpr int LL    = 4096;
constexpr int MM    = BB * LL;        // 32768 rows
constexpr int CHUNK = 64;
constexpr int NCH   = LL / CHUNK;     // 64 chunks per batch
constexpr int LDDBC = 24;             // padded leading dim for xdbl (r+2n <= 21)
constexpr float LN_EPS = 1e-5f;

// ----------------------------------------------------------------------------
// Static scratch (device globals: sanctioned alternative to cudaMalloc)
// ----------------------------------------------------------------------------
__device__ float g_bufA   [MM * 256];        // stage input activations
__device__ float g_bufXZ  [MM * 512];        // xz = [xc | z]
__device__ float g_bufConv[MM * 256];        // silu(conv(xc))
__device__ float g_bufDBC [MM * LDDBC];      // xdbl rows
__device__ float g_bufS   [MM * 256];        // per-step cumulative dt
__device__ float g_bufY   [MM * 256];        // scan output y
__device__ float g_bufMO  [MM * 256];        // mamba output (LN input)
__device__ float g_bufLN  [MM * 256];        // LN output
__device__ float g_chunkF [BB * NCH * 256 * 2];
__device__ float g_chunkS [BB * NCH * 256];
__device__ float g_hinit  [BB * NCH * 256 * 2];

// ----------------------------------------------------------------------------
// Helpers
// ----------------------------------------------------------------------------
__device__ __forceinline__ float silu_f(float v) {
    return v / (1.f + expf(-v));
}
__device__ __forceinline__ float softplus_f(float v) {
    return (v > 20.f) ? v : log1pf(expf(v));
}

// ----------------------------------------------------------------------------
// Transposes: x (b, C, L) <-> t (b, L, C)
// ----------------------------------------------------------------------------
__global__ void transpose_in_k(const float* __restrict__ x, float* __restrict__ t, int Cc) {
    __shared__ float tile[32][33];
    int b  = blockIdx.z;
    int l0 = blockIdx.x * 32;
    int c0 = blockIdx.y * 32;
    int tx = threadIdx.x, ty = threadIdx.y;
    #pragma unroll
    for (int i = 0; i < 32; i += 8)
        tile[ty + i][tx] = x[((size_t)b * Cc + c0 + ty + i) * LL + l0 + tx];
    __syncthreads();
    #pragma unroll
    for (int i = 0; i < 32; i += 8)
        t[((size_t)b * LL + l0 + ty + i) * Cc + c0 + tx] = tile[tx][ty + i];
}

__global__ void transpose_out_k(const float* __restrict__ t, float* __restrict__ o, int Cc) {
    __shared__ float tile[32][33];
    int b  = blockIdx.z;
    int l0 = blockIdx.x * 32;
    int c0 = blockIdx.y * 32;
    int tx = threadIdx.x, ty = threadIdx.y;
    #pragma unroll
    for (int i = 0; i < 32; i += 8)
        tile[ty + i][tx] = t[((size_t)b * LL + l0 + ty + i) * Cc + c0 + tx];
    __syncthreads();
    #pragma unroll
    for (int i = 0; i < 32; i += 8)
        o[((size_t)b * Cc + c0 + ty + i) * LL + l0 + tx] = tile[tx][ty + i];
}

// ----------------------------------------------------------------------------
// SIMT fp32 GEMM:  C[M,N] = A[M,K] @ W[N,K]^T (+bias) (EPI: 0 none, 1 silu)
// M multiple of BM; K multiple of BK; N guarded when NGUARD.
// ----------------------------------------------------------------------------
template <int BM, int BN, int BK, int TM, int TN, int EPI, bool NGUARD>
__global__ __launch_bounds__((BM / TM) * (BN / TN))
void gemm_k(const float* __restrict__ A, const float* __restrict__ W,
            const float* __restrict__ bias, float* __restrict__ C,
            int Mm, int Nn, int Kk, int ldc) {
    constexpr int THREADS = (BM / TM) * (BN / TN);
    constexpr int KV = BK / 4;
    __shared__ float As[BK][BM];
    __shared__ float Bs[BK][BN];
    const int tid  = threadIdx.x;
    const int m0   = blockIdx.y * BM;
    const int n0   = blockIdx.x * BN;
    const int tcol = tid % (BN / TN);
    const int trow = tid / (BN / TN);
    float acc[TM][TN];
    #pragma unroll
    for (int i = 0; i < TM; i++)
        #pragma unroll
        for (int j = 0; j < TN; j++) acc[i][j] = 0.f;

    for (int k0 = 0; k0 < Kk; k0 += BK) {
        #pragma unroll
        for (int idx = tid; idx < BM * KV; idx += THREADS) {
            int am = idx / KV, ak = idx % KV;
            float4 v = *reinterpret_cast<const float4*>(A + (size_t)(m0 + am) * Kk + k0 + ak * 4);
            As[ak * 4 + 0][am] = v.x; As[ak * 4 + 1][am] = v.y;
            As[ak * 4 + 2][am] = v.z; As[ak * 4 + 3][am] = v.w;
        }
        #pragma unroll
        for (int idx = tid; idx < BN * KV; idx += THREADS) {
            int bn = idx / KV, bk = idx % KV;
            float4 v = make_float4(0.f, 0.f, 0.f, 0.f);
            if (!NGUARD || (n0 + bn) < Nn)
                v = *reinterpret_cast<const float4*>(W + (size_t)(n0 + bn) * Kk + k0 + bk * 4);
            Bs[bk * 4 + 0][bn] = v.x; Bs[bk * 4 + 1][bn] = v.y;
            Bs[bk * 4 + 2][bn] = v.z; Bs[bk * 4 + 3][bn] = v.w;
        }
        __syncthreads();
        #pragma unroll
        for (int k = 0; k < BK; k++) {
            float ra[TM], rb[TN];
            #pragma unroll
            for (int i = 0; i < TM; i++) ra[i] = As[k][trow * TM + i];
            #pragma unroll
            for (int j = 0; j < TN; j++) rb[j] = Bs[k][tcol * TN + j];
            #pragma unroll
            for (int i = 0; i < TM; i++)
                #pragma unroll
                for (int j = 0; j < TN; j++) acc[i][j] += ra[i] * rb[j];
        }
        __syncthreads();
    }

    // Epilogue
    if (!NGUARD && (TN % 4 == 0)) {
        #pragma unroll
        for (int i = 0; i < TM; i++) {
            size_t base = (size_t)(m0 + trow * TM + i) * ldc + n0 + tcol * TN;
            #pragma unroll
            for (int jq = 0; jq < TN / 4; jq++) {
                float4 v;
                float t0 = acc[i][jq * 4 + 0], t1 = acc[i][jq * 4 + 1];
                float t2 = acc[i][jq * 4 + 2], t3 = acc[i][jq * 4 + 3];
                if (bias) {
                    int n = n0 + tcol * TN + jq * 4;
                    t0 += bias[n]; t1 += bias[n + 1]; t2 += bias[n + 2]; t3 += bias[n + 3];
                }
                if (EPI == 1) { t0 = silu_f(t0); t1 = silu_f(t1); t2 = silu_f(t2); t3 = silu_f(t3); }
                v.x = t0; v.y = t1; v.z = t2; v.w = t3;
                *reinterpret_cast<float4*>(&C[base + jq * 4]) = v;
            }
        }
    } else {
        #pragma unroll
        for (int i = 0; i < TM; i++) {
            int m = m0 + trow * TM + i;
            #pragma unroll
            for (int j = 0; j < TN; j++) {
                int n = n0 + tcol * TN + j;
                if (NGUARD && n >= Nn) continue;
                float v = acc[i][j];
                if (bias) v += bias[n];
                if (EPI == 1) v = silu_f(v);
                C[(size_t)m * ldc + n] = v;
            }
        }
    }
}

// ----------------------------------------------------------------------------
// Causal depthwise conv (k=4, pad (3,0)) + bias + silu.
// Reads xc columns [0,D) of xz rows (ld = 2D).
// ----------------------------------------------------------------------------
__global__ void conv_silu_k(const float* __restrict__ xz, const float* __restrict__ cw,
                            const float* __restrict__ cb, float* __restrict__ out, int D) {
    int d = blockIdx.x * blockDim.x + threadIdx.x;
    int l = blockIdx.y, b = blockIdx.z;
    if (d >= D) return;
    int ld = 2 * D;
    size_t rowb = (size_t)b * LL + l;
    float w0 = cw[d * 4], w1 = cw[d * 4 + 1], w2 = cw[d * 4 + 2], w3 = cw[d * 4 + 3];
    float acc = cb[d];
    if (l >= 3) acc += xz[(rowb - 3) * ld + d] * w0;
    if (l >= 2) acc += xz[(rowb - 2) * ld + d] * w1;
    if (l >= 1) acc += xz[(rowb - 1) * ld + d] * w2;
    acc += xz[rowb * ld + d] * w3;
    out[rowb * D + d] = silu_f(acc);
}

// ----------------------------------------------------------------------------
// Chunked parallel scan.
// Phase A: local scan per chunk (h_init = 0). Also computes dt on the fly:
//   dt = softplus(wdt . xdbl[:r] + bdt). Stores per-step y_local and S_t
//   (cumulative dt, inclusive), plus chunk-final (h, S).
// ----------------------------------------------------------------------------
template <int R>
__global__ void scanA_k(const float* __restrict__ dbc, const float* __restrict__ conv,
                        const float* __restrict__ wdt, const float* __restrict__ bdt,
                        const float* __restrict__ alog,
                        float* __restrict__ ybuf, float* __restrict__ sbuf,
                        float* __restrict__ chF, float* __restrict__ chS, int D) {
    __shared__ float sh[CHUNK * LDDBC];
    int d = threadIdx.x, ch = blockIdx.x, b = blockIdx.y;
    size_t lbase = (size_t)b * LL + ch * CHUNK;
    for (int idx = d; idx < CHUNK * LDDBC; idx += D)
        sh[idx] = dbc[lbase * LDDBC + idx];
    float wr[R];
    #pragma unroll
    for (int q = 0; q < R; q++) wr[q] = wdt[d * R + q];
    float A0 = -expf(alog[d * 2 + 0]);
    float A1 = -expf(alog[d * 2 + 1]);
    float bd = bdt[d];
    float h0 = 0.f, h1 = 0.f, S = 0.f;
    __syncthreads();
    for (int t0 = 0; t0 < CHUNK; t0 += 8) {
        float xcv[8];
        #pragma unroll
        for (int i = 0; i < 8; i++) xcv[i] = conv[(lbase + t0 + i) * D + d];
        #pragma unroll
        for (int i = 0; i < 8; i++) {
            const float* row = &sh[(t0 + i) * LDDBC];
            float dtr = bd;
            #pragma unroll
            for (int q = 0; q < R; q++) dtr += wr[q] * row[q];
            float dt = softplus_f(dtr);
            S += dt;
            float u = dt * xcv[i];
            h0 = expf(dt * A0) * h0 + u * row[R];
            h1 = expf(dt * A1) * h1 + u * row[R + 1];
            ybuf[(lbase + t0 + i) * D + d] = h0 * row[R + 2] + h1 * row[R + 3];
            sbuf[(lbase + t0 + i) * D + d] = S;
        }
    }
    size_t ci = ((size_t)(b * NCH + ch)) * D + d;
    chF[ci * 2 + 0] = h0;
    chF[ci * 2 + 1] = h1;
    chS[ci] = S;
}

// Phase B: sequential prefix over chunks per (b, d, j). h_init[ch] = state
// entering chunk ch. Exact because prod(dA over chunk) = exp(A * sum(dt)).
__global__ void scanB_k(const float* __restrict__ chF, const float* __restrict__ chS,
                        const float* __restrict__ alog, float* __restrict__ hinit, int D) {
    int idx = blockIdx.x * blockDim.x + threadIdx.x;
    if (idx >= BB * D * 2) return;
    int j = idx & 1;
    int d = (idx >> 1) % D;
    int b = idx / (2 * D);
    float A = -expf(alog[d * 2 + j]);
    float H = 0.f;
    for (int ch = 0; ch < NCH; ch++) {
        size_t ci = ((size_t)(b * NCH + ch)) * D + d;
        hinit[ci * 2 + j] = H;
        H = expf(A * chS[ci]) * H + chF[ci * 2 + j];
    }
}

// Phase C: correction + epilogue:
//   y = (y_local + sum_j exp(A_j*S_t)*hinit_j*C_t_j + dd*xc) * silu(z)
__global__ void scanC_k(const float* __restrict__ dbc, const float* __restrict__ conv,
                        const float* __restrict__ xz, const float* __restrict__ hinit,
                        const float* __restrict__ alog, const float* __restrict__ dd,
                        const float* __restrict__ sbuf, float* __restrict__ ybuf,
                        int D, int r) {
    __shared__ float sh[CHUNK * LDDBC];
    int d = threadIdx.x, ch = blockIdx.x, b = blockIdx.y;
    size_t lbase = (size_t)b * LL + ch * CHUNK;
    for (int idx = d; idx < CHUNK * LDDBC; idx += D)
        sh[idx] = dbc[lbase * LDDBC + idx];
    float A0 = -expf(alog[d * 2 + 0]);
    float A1 = -expf(alog[d * 2 + 1]);
    size_t ci = ((size_t)(b * NCH + ch)) * D + d;
    float h00 = hinit[ci * 2 + 0], h01 = hinit[ci * 2 + 1];
    float ddv = dd[d];
    int ld2 = 2 * D;
    __syncthreads();
    for (int t0 = 0; t0 < CHUNK; t0 += 8) {
        float xcv[8], zv[8], Sv[8], ylv[8];
        #pragma unroll
        for (int i = 0; i < 8; i++) {
            size_t rb = lbase + t0 + i;
            xcv[i] = conv[rb * D + d];
            zv[i]  = xz[rb * ld2 + D + d];
            Sv[i]  = sbuf[rb * D + d];
            ylv[i] = ybuf[rb * D + d];
        }
        #pragma unroll
        for (int i = 0; i < 8; i++) {
            const float* row = &sh[(t0 + i) * LDDBC];
            float y = ylv[i]
                    + expf(A0 * Sv[i]) * h00 * row[r + 2]
                    + expf(A1 * Sv[i]) * h01 * row[r + 3]
                    + ddv * xcv[i];
            y *= silu_f(zv[i]);
            ybuf[(lbase + t0 + i) * D + d] = y;
        }
    }
}

// ----------------------------------------------------------------------------
// LayerNorm over last dim (block per row, D threads)
// ----------------------------------------------------------------------------
__global__ void ln_k(const float* __restrict__ in, const float* __restrict__ w,
                     const float* __restrict__ bgm, float* __restrict__ out, int D) {
    int m = blockIdx.x, d = threadIdx.x;
    float v = in[(size_t)m * D + d];
    float s = v, sq = v * v;
    #pragma unroll
    for (int o = 16; o > 0; o >>= 1) {
        s  += __shfl_xor_sync(0xffffffffu, s,  o);
        sq += __shfl_xor_sync(0xffffffffu, sq, o);
    }
    __shared__ float ws[8], wq[8];
    __shared__ float mu_s, rstd_s;
    int warp = d >> 5, lane = d & 31, nw = D >> 5;
    if (lane == 0) { ws[warp] = s; wq[warp] = sq; }
    __syncthreads();
    if (d == 0) {
        float ts = 0.f, tq = 0.f;
        for (int i = 0; i < nw; i++) { ts += ws[i]; tq += wq[i]; }
        float mu  = ts / D;
        float var = tq / D - mu * mu;
        mu_s = mu;
        rstd_s = rsqrtf(var + LN_EPS);
    }
    __syncthreads();
    out[(size_t)m * D + d] = (v - mu_s) * rstd_s * w[d] + bgm[d];
}

// ----------------------------------------------------------------------------
// Host-side driver
// ----------------------------------------------------------------------------
struct Bufs {
    float *A, *XZ, *Conv, *DBC, *S, *Y, *MO, *LN, *chF, *chS, *hin;
};

static void run_stage(const float* const* p, const float* bufIn, int D, int R, const Bufs& bf) {
    // 1. xz = X @ win^T + b_in
    gemm_k<128, 128, 16, 8, 8, 0, false>
        <<<dim3(2 * D / 128, MM / 128), 256>>>(bufIn, p[0], p[1], bf.XZ, MM, 2 * D, D, 2 * D);
    // 2. conv + silu
    conv_silu_k<<<dim3(D / 128, LL, BB), 128>>>(bf.XZ, p[2], p[3], bf.Conv, D);
    // 3. xdbl = xc @ wx^T (thin)
    gemm_k<128, 32, 16, 8, 2, 0, true>
        <<<dim3(1, MM / 128), 256>>>(bf.Conv, p[4], nullptr, bf.DBC, MM, R + 4, D, LDDBC);
    // 4-6. chunked scan
    if (R == 9)
        scanA_k<9><<<dim3(NCH, BB), D>>>(bf.DBC, bf.Conv, p[5], p[6], p[7], bf.Y, bf.S, bf.chF, bf.chS, D);
    else
        scanA_k<17><<<dim3(NCH, BB), D>>>(bf.DBC, bf.Conv, p[5], p[6], p[7], bf.Y, bf.S, bf.chF, bf.chS, D);
    scanB_k<<<(BB * D * 2 + 255) / 256, 256>>>(bf.chF, bf.chS, p[7], bf.hin, D);
    scanC_k<<<dim3(NCH, BB), D>>>(bf.DBC, bf.Conv, bf.XZ, bf.hin, p[7], p[8], bf.S, bf.Y, D, R);
    // 7. out = y @ wout^T
    gemm_k<128, 128, 16, 8, 8, 0, false>
        <<<dim3(D / 128, MM / 128), 256>>>(bf.Y, p[9], nullptr, bf.MO, MM, D, D, D);
    // 8. layernorm
    ln_k<<<MM, D>>>(bf.MO, p[10], p[11], bf.LN, D);
}

extern "C" void kernel_launch(void* const* d_in, const int* in_sizes, int n_in,
                              void* d_out, int out_size) {
    const float* x     = (const float*)d_in[0];
    const float* lin_w = (const float*)d_in[1];
    const float* lin_b = (const float*)d_in[2];
    const float* p1[12];
    const float* p2[12];
    for (int i = 0; i < 12; i++) p1[i] = (const float*)d_in[3 + i];
    for (int i = 0; i < 12; i++) p2[i] = (const float*)d_in[15 + i];
    float* out = (float*)d_out;

    Bufs bf;
    void* p;
    cudaGetSymbolAddress(&p, g_bufA);    bf.A    = (float*)p;
    cudaGetSymbolAddress(&p, g_bufXZ);   bf.XZ   = (float*)p;
    cudaGetSymbolAddress(&p, g_bufConv); bf.Conv = (float*)p;
    cudaGetSymbolAddress(&p, g_bufDBC);  bf.DBC  = (float*)p;
    cudaGetSymbolAddress(&p, g_bufS);    bf.S    = (float*)p;
    cudaGetSymbolAddress(&p, g_bufY);    bf.Y    = (float*)p;
    cudaGetSymbolAddress(&p, g_bufMO);   bf.MO   = (float*)p;
    cudaGetSymbolAddress(&p, g_bufLN);   bf.LN   = (float*)p;
    cudaGetSymbolAddress(&p, g_chunkF);  bf.chF  = (float*)p;
    cudaGetSymbolAddress(&p, g_chunkS);  bf.chS  = (float*)p;
    cudaGetSymbolAddress(&p, g_hinit);   bf.hin  = (float*)p;

    // Input transpose: x (8,128,4096) -> t (32768,128)
    transpose_in_k<<<dim3(LL / 32, 128 / 32, BB), dim3(32, 8)>>>(x, bf.A, 128);

    // Stage 1 (d=128, r=9)
    run_stage(p1, bf.A, 128, 9, bf);

    // Inter-stage linear + silu: (M,128)@(256,128)^T
    gemm_k<128, 128, 16, 8, 8, 1, false>
        <<<dim3(2, MM / 128), 256>>>(bf.LN, lin_w, lin_b, bf.A, MM, 256, 128, 256);

    // Stage 2 (d=256, r=17)
    run_stage(p2, bf.A, 256, 17, bf);

    // Output transpose: t (32768,256) -> out (8,256,4096)
    transpose_out_k<<<dim3(LL / 32, 256 / 32, BB), dim3(32, 8)>>>(bf.LN, out, 256);
}

// round 5
// speedup vs baseline: 1.3818x; 1.3818x over previous
#include <cuda_runtime.h>
#include <cuda_bf16.h>
#include <cstdint>
#include <cstdio>

// ----------------------------------------------------------------------------
// Problem constants
// ----------------------------------------------------------------------------
constexpr int BB    = 8;
constexpr int LL    = 4096;
constexpr int MM    = BB * LL;        // 32768 rows
constexpr int CHUNK = 64;
constexpr int NCH   = LL / CHUNK;     // 64 chunks per batch
constexpr int LDDBC = 24;             // padded leading dim for xdbl (r+2n <= 21)
constexpr float LN_EPS = 1e-5f;

// ----------------------------------------------------------------------------
// Static scratch (device globals: sanctioned alternative to cudaMalloc)
// ----------------------------------------------------------------------------
__device__ float g_bufA   [MM * 256];        // stage input activations
__device__ float g_bufXZ  [MM * 512];        // xz = [xc | z]
__device__ float g_bufConv[MM * 256];        // silu(conv(xc))
__device__ float g_bufDBC [MM * LDDBC];      // xdbl rows
__device__ float g_bufS   [MM * 256];        // per-step cumulative dt
__device__ float g_bufY   [MM * 256];        // scan output y
__device__ float g_bufMO  [MM * 256];        // mamba output (LN input)
__device__ float g_bufLN  [MM * 256];        // LN output
__device__ float g_chunkF [BB * NCH * 256 * 2];
__device__ float g_chunkS [BB * NCH * 256];
__device__ float g_hinit  [BB * NCH * 256 * 2];

// ----------------------------------------------------------------------------
// Helpers
// ----------------------------------------------------------------------------
__device__ __forceinline__ float silu_f(float v) {
    return v / (1.f + expf(-v));
}
__device__ __forceinline__ float softplus_f(float v) {
    return (v > 20.f) ? v : log1pf(expf(v));
}

__device__ __forceinline__ uint32_t smem_to_u32(const void* smem_ptr) {
    uint32_t addr;
    asm("{ .reg .u64 tmp; cvta.to.shared.u64 tmp, %1; cvt.u32.u64 %0, tmp; }"
        : "=r"(addr) : "l"(smem_ptr));
    return addr;
}

// ldmatrix x4 (four 8x8 b16 matrices)
__device__ __forceinline__ void ldsm4(uint32_t* r, uint32_t addr) {
    asm volatile("ldmatrix.sync.aligned.m8n8.x4.shared.b16 {%0,%1,%2,%3}, [%4];"
        : "=r"(r[0]), "=r"(r[1]), "=r"(r[2]), "=r"(r[3]) : "r"(addr));
}

// D += A * B  (m16n8k16, bf16 in, fp32 acc)
__device__ __forceinline__ void mma16816(float* c, const uint32_t* a,
                                         uint32_t b0, uint32_t b1) {
    asm volatile(
        "mma.sync.aligned.m16n8k16.row.col.f32.bf16.bf16.f32 "
        "{%0,%1,%2,%3}, {%4,%5,%6,%7}, {%8,%9}, {%0,%1,%2,%3};"
        : "+f"(c[0]), "+f"(c[1]), "+f"(c[2]), "+f"(c[3])
        : "r"(a[0]), "r"(a[1]), "r"(a[2]), "r"(a[3]), "r"(b0), "r"(b1));
}

// ----------------------------------------------------------------------------
// Tensor-core GEMM via mma.sync: C[M,N] = A[M,K] @ W[N,K]^T (+bias) (epi 1=silu)
// fp32 I/O; bf16 hi/lo 3-term split internally (residual ~2^-16).
// CTA: 256 threads (8 warps, 2x4), tile 128x128, BK=32, double-buffered smem.
// smem tile layout (per operand, bf16 [128 rows][32 k]): row stride 64B,
//   off(r,k) = r*64 + (((k>>3) ^ ((r>>1)&3))<<4) + (k&7)*2   (conflict-free
//   for both the STS write pattern and all ldmatrix.x4 transfers).
// ----------------------------------------------------------------------------
constexpr int GSM_STAGE = 32768;               // Ah(8K)+Al(8K)+Bh(8K)+Bl(8K)
constexpr int GSM_TOTAL = 2 * GSM_STAGE;       // double buffer

__global__ __launch_bounds__(256) void mma_gemm_k(
    const float* __restrict__ A, const float* __restrict__ W,
    const float* __restrict__ bias, float* __restrict__ C,
    int Nn, int Kk, int epi) {
    extern __shared__ char smem[];
    const uint32_t sb = smem_to_u32(smem);
    const int tid  = threadIdx.x;
    const int lane = tid & 31;
    const int w    = tid >> 5;
    const int wm   = w >> 2;          // 0..1
    const int wn   = w & 3;           // 0..3
    const int m0 = blockIdx.y * 128;
    const int n0 = blockIdx.x * 128;

    // ldmatrix per-thread addressing
    const int g  = lane >> 3;         // matrix id 0..3
    const int lr = lane & 7;
    const int gk = g >> 1;            // k-chunk offset contributed by matrix id
    const int arow = wm * 64 + lr + ((g & 1) << 3);
    const int brow = wn * 32 + lr + ((g & 1) << 3);
    const int s_a = (arow >> 1) & 3;
    const int s_b = (brow >> 1) & 3;
    const uint32_t aoff = sb + (uint32_t)arow * 64;           // into Ah
    const uint32_t boff = sb + 16384u + (uint32_t)brow * 64;  // into Bh

    float acc[4][4][4];
    #pragma unroll
    for (int i = 0; i < 4; i++)
        #pragma unroll
        for (int j = 0; j < 4; j++)
            #pragma unroll
            for (int q = 0; q < 4; q++) acc[i][j][q] = 0.f;

    const int nch = Kk >> 5;
    float2 pfA[8], pfB[8];

    // prologue: fetch + stage chunk 0
    {
        #pragma unroll
        for (int i = 0; i < 8; i++) {
            int p = tid + (i << 8);
            int row = p >> 4, pc = p & 15;
            pfA[i] = *reinterpret_cast<const float2*>(A + (size_t)(m0 + row) * Kk + pc * 2);
            pfB[i] = *reinterpret_cast<const float2*>(W + (size_t)(n0 + row) * Kk + pc * 2);
        }
        #pragma unroll
        for (int i = 0; i < 8; i++) {
            int p = tid + (i << 8);
            int row = p >> 4, pc = p & 15;
            uint32_t off = (uint32_t)(row * 64 + (((pc >> 2) ^ ((row >> 1) & 3)) << 4) + (pc & 3) * 4);
            float2 va = pfA[i];
            __nv_bfloat162 ha = __floats2bfloat162_rn(va.x, va.y);
            __nv_bfloat162 la = __floats2bfloat162_rn(va.x - __bfloat162float(ha.x),
                                                      va.y - __bfloat162float(ha.y));
            *reinterpret_cast<uint32_t*>(smem + off)         = *reinterpret_cast<uint32_t*>(&ha);
            *reinterpret_cast<uint32_t*>(smem + 8192 + off)  = *reinterpret_cast<uint32_t*>(&la);
            float2 vb = pfB[i];
            __nv_bfloat162 hb = __floats2bfloat162_rn(vb.x, vb.y);
            __nv_bfloat162 lb = __floats2bfloat162_rn(vb.x - __bfloat162float(hb.x),
                                                      vb.y - __bfloat162float(hb.y));
            *reinterpret_cast<uint32_t*>(smem + 16384 + off) = *reinterpret_cast<uint32_t*>(&hb);
            *reinterpret_cast<uint32_t*>(smem + 24576 + off) = *reinterpret_cast<uint32_t*>(&lb);
        }
    }

    for (int c = 0; c < nch; c++) {
        __syncthreads();
        // prefetch next chunk into registers (overlaps with MMA below)
        if (c + 1 < nch) {
            const int k0 = (c + 1) << 5;
            #pragma unroll
            for (int i = 0; i < 8; i++) {
                int p = tid + (i << 8);
                int row = p >> 4, pc = p & 15;
                pfA[i] = *reinterpret_cast<const float2*>(A + (size_t)(m0 + row) * Kk + k0 + pc * 2);
                pfB[i] = *reinterpret_cast<const float2*>(W + (size_t)(n0 + row) * Kk + k0 + pc * 2);
            }
        }
        // compute on buffer c&1
        const uint32_t sA = aoff + (uint32_t)(c & 1) * GSM_STAGE;
        const uint32_t sB = boff + (uint32_t)(c & 1) * GSM_STAGE;
        #pragma unroll
        for (int ks = 0; ks < 2; ks++) {
            const uint32_t coA = (uint32_t)((((ks << 1) + gk) ^ s_a) << 4);
            const uint32_t coB = (uint32_t)((((ks << 1) + gk) ^ s_b) << 4);
            uint32_t aH[4][4], aL[4][4], bH[2][4], bL[2][4];
            #pragma unroll
            for (int mi = 0; mi < 4; mi++) {
                ldsm4(aH[mi], sA + mi * 1024 + coA);
                ldsm4(aL[mi], sA + 8192 + mi * 1024 + coA);
            }
            #pragma unroll
            for (int np = 0; np < 2; np++) {
                ldsm4(bH[np], sB + np * 1024 + coB);
                ldsm4(bL[np], sB + 8192 + np * 1024 + coB);
            }
            #pragma unroll
            for (int mi = 0; mi < 4; mi++)
                #pragma unroll
                for (int ni = 0; ni < 4; ni++) {
                    const int np = ni >> 1, sel = ni & 1;
                    mma16816(acc[mi][ni], aH[mi], bH[np][sel], bH[np][sel + 2]);
                    mma16816(acc[mi][ni], aL[mi], bH[np][sel], bH[np][sel + 2]);
                    mma16816(acc[mi][ni], aH[mi], bL[np][sel], bL[np][sel + 2]);
                }
        }
        // stage next chunk (targets buffer (c+1)&1, last read in iter c-1: safe)
        if (c + 1 < nch) {
            char* dst = smem + ((c + 1) & 1) * GSM_STAGE;
            #pragma unroll
            for (int i = 0; i < 8; i++) {
                int p = tid + (i << 8);
                int row = p >> 4, pc = p & 15;
                uint32_t off = (uint32_t)(row * 64 + (((pc >> 2) ^ ((row >> 1) & 3)) << 4) + (pc & 3) * 4);
                float2 va = pfA[i];
                __nv_bfloat162 ha = __floats2bfloat162_rn(va.x, va.y);
                __nv_bfloat162 la = __floats2bfloat162_rn(va.x - __bfloat162float(ha.x),
                                                          va.y - __bfloat162float(ha.y));
                *reinterpret_cast<uint32_t*>(dst + off)         = *reinterpret_cast<uint32_t*>(&ha);
                *reinterpret_cast<uint32_t*>(dst + 8192 + off)  = *reinterpret_cast<uint32_t*>(&la);
                float2 vb = pfB[i];
                __nv_bfloat162 hb = __floats2bfloat162_rn(vb.x, vb.y);
                __nv_bfloat162 lb = __floats2bfloat162_rn(vb.x - __bfloat162float(hb.x),
                                                          vb.y - __bfloat162float(hb.y));
                *reinterpret_cast<uint32_t*>(dst + 16384 + off) = *reinterpret_cast<uint32_t*>(&hb);
                *reinterpret_cast<uint32_t*>(dst + 24576 + off) = *reinterpret_cast<uint32_t*>(&lb);
            }
        }
    }

    // epilogue: bias (+silu) and store, float2 per (mi, ni, half)
    #pragma unroll
    for (int mi = 0; mi < 4; mi++) {
        #pragma unroll
        for (int ni = 0; ni < 4; ni++) {
            const int gr = m0 + wm * 64 + mi * 16 + (lane >> 2);
            const int gc = n0 + wn * 32 + ni * 8 + (lane & 3) * 2;
            float b0 = 0.f, b1 = 0.f;
            if (bias) { b0 = bias[gc]; b1 = bias[gc + 1]; }
            float v0 = acc[mi][ni][0] + b0, v1 = acc[mi][ni][1] + b1;
            float v2 = acc[mi][ni][2] + b0, v3 = acc[mi][ni][3] + b1;
            if (epi == 1) { v0 = silu_f(v0); v1 = silu_f(v1); v2 = silu_f(v2); v3 = silu_f(v3); }
            float2 lo; lo.x = v0; lo.y = v1;
            float2 hi; hi.x = v2; hi.y = v3;
            *reinterpret_cast<float2*>(&C[(size_t)gr * Nn + gc])       = lo;
            *reinterpret_cast<float2*>(&C[(size_t)(gr + 8) * Nn + gc]) = hi;
        }
    }
}

// ----------------------------------------------------------------------------
// Transposes: x (b, C, L) <-> t (b, L, C)
// ----------------------------------------------------------------------------
__global__ void transpose_in_k(const float* __restrict__ x, float* __restrict__ t, int Cc) {
    __shared__ float tile[32][33];
    int b  = blockIdx.z;
    int l0 = blockIdx.x * 32;
    int c0 = blockIdx.y * 32;
    int tx = threadIdx.x, ty = threadIdx.y;
    #pragma unroll
    for (int i = 0; i < 32; i += 8)
        tile[ty + i][tx] = x[((size_t)b * Cc + c0 + ty + i) * LL + l0 + tx];
    __syncthreads();
    #pragma unroll
    for (int i = 0; i < 32; i += 8)
        t[((size_t)b * LL + l0 + ty + i) * Cc + c0 + tx] = tile[tx][ty + i];
}

__global__ void transpose_out_k(const float* __restrict__ t, float* __restrict__ o, int Cc) {
    __shared__ float tile[32][33];
    int b  = blockIdx.z;
    int l0 = blockIdx.x * 32;
    int c0 = blockIdx.y * 32;
    int tx = threadIdx.x, ty = threadIdx.y;
    #pragma unroll
    for (int i = 0; i < 32; i += 8)
        tile[ty + i][tx] = t[((size_t)b * LL + l0 + ty + i) * Cc + c0 + tx];
    __syncthreads();
    #pragma unroll
    for (int i = 0; i < 32; i += 8)
        o[((size_t)b * Cc + c0 + ty + i) * LL + l0 + tx] = tile[tx][ty + i];
}

// ----------------------------------------------------------------------------
// SIMT fp32 GEMM (kept for the thin xdbl projection only)
// ----------------------------------------------------------------------------
template <int BM, int BN, int BK, int TM, int TN, int EPI, bool NGUARD>
__global__ __launch_bounds__((BM / TM) * (BN / TN))
void gemm_k(const float* __restrict__ A, const float* __restrict__ W,
            const float* __restrict__ bias, float* __restrict__ C,
            int Mm, int Nn, int Kk, int ldc) {
    constexpr int THREADS = (BM / TM) * (BN / TN);
    constexpr int KV = BK / 4;
    __shared__ float As[BK][BM];
    __shared__ float Bs[BK][BN];
    const int tid  = threadIdx.x;
    const int m0   = blockIdx.y * BM;
    const int n0   = blockIdx.x * BN;
    const int tcol = tid % (BN / TN);
    const int trow = tid / (BN / TN);
    float acc[TM][TN];
    #pragma unroll
    for (int i = 0; i < TM; i++)
        #pragma unroll
        for (int j = 0; j < TN; j++) acc[i][j] = 0.f;

    for (int k0 = 0; k0 < Kk; k0 += BK) {
        #pragma unroll
        for (int idx = tid; idx < BM * KV; idx += THREADS) {
            int am = idx / KV, ak = idx % KV;
            float4 v = *reinterpret_cast<const float4*>(A + (size_t)(m0 + am) * Kk + k0 + ak * 4);
            As[ak * 4 + 0][am] = v.x; As[ak * 4 + 1][am] = v.y;
            As[ak * 4 + 2][am] = v.z; As[ak * 4 + 3][am] = v.w;
        }
        #pragma unroll
        for (int idx = tid; idx < BN * KV; idx += THREADS) {
            int bn = idx / KV, bk = idx % KV;
            float4 v = make_float4(0.f, 0.f, 0.f, 0.f);
            if (!NGUARD || (n0 + bn) < Nn)
                v = *reinterpret_cast<const float4*>(W + (size_t)(n0 + bn) * Kk + k0 + bk * 4);
            Bs[bk * 4 + 0][bn] = v.x; Bs[bk * 4 + 1][bn] = v.y;
            Bs[bk * 4 + 2][bn] = v.z; Bs[bk * 4 + 3][bn] = v.w;
        }
        __syncthreads();
        #pragma unroll
        for (int k = 0; k < BK; k++) {
            float ra[TM], rb[TN];
            #pragma unroll
            for (int i = 0; i < TM; i++) ra[i] = As[k][trow * TM + i];
            #pragma unroll
            for (int j = 0; j < TN; j++) rb[j] = Bs[k][tcol * TN + j];
            #pragma unroll
            for (int i = 0; i < TM; i++)
                #pragma unroll
                for (int j = 0; j < TN; j++) acc[i][j] += ra[i] * rb[j];
        }
        __syncthreads();
    }

    #pragma unroll
    for (int i = 0; i < TM; i++) {
        int m = m0 + trow * TM + i;
        #pragma unroll
        for (int j = 0; j < TN; j++) {
            int n = n0 + tcol * TN + j;
            if (NGUARD && n >= Nn) continue;
            float v = acc[i][j];
            if (bias) v += bias[n];
            if (EPI == 1) v = silu_f(v);
            C[(size_t)m * ldc + n] = v;
        }
    }
}

// ----------------------------------------------------------------------------
// Causal depthwise conv (k=4, pad (3,0)) + bias + silu.
// ----------------------------------------------------------------------------
__global__ void conv_silu_k(const float* __restrict__ xz, const float* __restrict__ cw,
                            const float* __restrict__ cb, float* __restrict__ out, int D) {
    int d = blockIdx.x * blockDim.x + threadIdx.x;
    int l = blockIdx.y, b = blockIdx.z;
    if (d >= D) return;
    int ld = 2 * D;
    size_t rowb = (size_t)b * LL + l;
    float w0 = cw[d * 4], w1 = cw[d * 4 + 1], w2 = cw[d * 4 + 2], w3 = cw[d * 4 + 3];
    float acc = cb[d];
    if (l >= 3) acc += xz[(rowb - 3) * ld + d] * w0;
    if (l >= 2) acc += xz[(rowb - 2) * ld + d] * w1;
    if (l >= 1) acc += xz[(rowb - 1) * ld + d] * w2;
    acc += xz[rowb * ld + d] * w3;
    out[rowb * D + d] = silu_f(acc);
}

// ----------------------------------------------------------------------------
// Chunked parallel scan (phases A, B, C)
// ----------------------------------------------------------------------------
template <int R>
__global__ void scanA_k(const float* __restrict__ dbc, const float* __restrict__ conv,
                        const float* __restrict__ wdt, const float* __restrict__ bdt,
                        const float* __restrict__ alog,
                        float* __restrict__ ybuf, float* __restrict__ sbuf,
                        float* __restrict__ chF, float* __restrict__ chS, int D) {
    __shared__ float sh[CHUNK * LDDBC];
    int d = threadIdx.x, ch = blockIdx.x, b = blockIdx.y;
    size_t lbase = (size_t)b * LL + ch * CHUNK;
    for (int idx = d; idx < CHUNK * LDDBC; idx += D)
        sh[idx] = dbc[lbase * LDDBC + idx];
    float wr[R];
    #pragma unroll
    for (int q = 0; q < R; q++) wr[q] = wdt[d * R + q];
    float A0 = -expf(alog[d * 2 + 0]);
    float A1 = -expf(alog[d * 2 + 1]);
    float bd = bdt[d];
    float h0 = 0.f, h1 = 0.f, S = 0.f;
    __syncthreads();
    for (int t0 = 0; t0 < CHUNK; t0 += 8) {
        float xcv[8];
        #pragma unroll
        for (int i = 0; i < 8; i++) xcv[i] = conv[(lbase + t0 + i) * D + d];
        #pragma unroll
        for (int i = 0; i < 8; i++) {
            const float* row = &sh[(t0 + i) * LDDBC];
            float dtr = bd;
            #pragma unroll
            for (int q = 0; q < R; q++) dtr += wr[q] * row[q];
            float dt = softplus_f(dtr);
            S += dt;
            float u = dt * xcv[i];
            h0 = expf(dt * A0) * h0 + u * row[R];
            h1 = expf(dt * A1) * h1 + u * row[R + 1];
            ybuf[(lbase + t0 + i) * D + d] = h0 * row[R + 2] + h1 * row[R + 3];
            sbuf[(lbase + t0 + i) * D + d] = S;
        }
    }
    size_t ci = ((size_t)(b * NCH + ch)) * D + d;
    chF[ci * 2 + 0] = h0;
    chF[ci * 2 + 1] = h1;
    chS[ci] = S;
}

__global__ void scanB_k(const float* __restrict__ chF, const float* __restrict__ chS,
                        const float* __restrict__ alog, float* __restrict__ hinit, int D) {
    int idx = blockIdx.x * blockDim.x + threadIdx.x;
    if (idx >= BB * D * 2) return;
    int j = idx & 1;
    int d = (idx >> 1) % D;
    int b = idx / (2 * D);
    float A = -expf(alog[d * 2 + j]);
    float H = 0.f;
    for (int ch = 0; ch < NCH; ch++) {
        size_t ci = ((size_t)(b * NCH + ch)) * D + d;
        hinit[ci * 2 + j] = H;
        H = expf(A * chS[ci]) * H + chF[ci * 2 + j];
    }
}

__global__ void scanC_k(const float* __restrict__ dbc, const float* __restrict__ conv,
                        const float* __restrict__ xz, const float* __restrict__ hinit,
                        const float* __restrict__ alog, const float* __restrict__ dd,
                        const float* __restrict__ sbuf, float* __restrict__ ybuf,
                        int D, int r) {
    __shared__ float sh[CHUNK * LDDBC];
    int d = threadIdx.x, ch = blockIdx.x, b = blockIdx.y;
    size_t lbase = (size_t)b * LL + ch * CHUNK;
    for (int idx = d; idx < CHUNK * LDDBC; idx += D)
        sh[idx] = dbc[lbase * LDDBC + idx];
    float A0 = -expf(alog[d * 2 + 0]);
    float A1 = -expf(alog[d * 2 + 1]);
    size_t ci = ((size_t)(b * NCH + ch)) * D + d;
    float h00 = hinit[ci * 2 + 0], h01 = hinit[ci * 2 + 1];
    float ddv = dd[d];
    int ld2 = 2 * D;
    __syncthreads();
    for (int t0 = 0; t0 < CHUNK; t0 += 8) {
        float xcv[8], zv[8], Sv[8], ylv[8];
        #pragma unroll
        for (int i = 0; i < 8; i++) {
            size_t rb = lbase + t0 + i;
            xcv[i] = conv[rb * D + d];
            zv[i]  = xz[rb * ld2 + D + d];
            Sv[i]  = sbuf[rb * D + d];
            ylv[i] = ybuf[rb * D + d];
        }
        #pragma unroll
        for (int i = 0; i < 8; i++) {
            const float* row = &sh[(t0 + i) * LDDBC];
            float y = ylv[i]
                    + expf(A0 * Sv[i]) * h00 * row[r + 2]
                    + expf(A1 * Sv[i]) * h01 * row[r + 3]
                    + ddv * xcv[i];
            y *= silu_f(zv[i]);
            ybuf[(lbase + t0 + i) * D + d] = y;
        }
    }
}

// ----------------------------------------------------------------------------
// LayerNorm over last dim (block per row, D threads)
// ----------------------------------------------------------------------------
__global__ void ln_k(const float* __restrict__ in, const float* __restrict__ w,
                     const float* __restrict__ bgm, float* __restrict__ out, int D) {
    int m = blockIdx.x, d = threadIdx.x;
    float v = in[(size_t)m * D + d];
    float s = v, sq = v * v;
    #pragma unroll
    for (int o = 16; o > 0; o >>= 1) {
        s  += __shfl_xor_sync(0xffffffffu, s,  o);
        sq += __shfl_xor_sync(0xffffffffu, sq, o);
    }
    __shared__ float ws[8], wq[8];
    __shared__ float mu_s, rstd_s;
    int warp = d >> 5, lane = d & 31, nw = D >> 5;
    if (lane == 0) { ws[warp] = s; wq[warp] = sq; }
    __syncthreads();
    if (d == 0) {
        float ts = 0.f, tq = 0.f;
        for (int i = 0; i < nw; i++) { ts += ws[i]; tq += wq[i]; }
        float mu  = ts / D;
        float var = tq / D - mu * mu;
        mu_s = mu;
        rstd_s = rsqrtf(var + LN_EPS);
    }
    __syncthreads();
    out[(size_t)m * D + d] = (v - mu_s) * rstd_s * w[d] + bgm[d];
}

// ----------------------------------------------------------------------------
// Host-side driver
// ----------------------------------------------------------------------------
struct Bufs {
    float *A, *XZ, *Conv, *DBC, *S, *Y, *MO, *LN, *chF, *chS, *hin;
};

static void mma_gemm(const float* A, const float* W, const float* bias, float* C,
                     int N, int K, int epi) {
    mma_gemm_k<<<dim3(N / 128, MM / 128), 256, GSM_TOTAL>>>(A, W, bias, C, N, K, epi);
}

static void run_stage(const float* const* p, const float* bufIn, int D, int R, const Bufs& bf) {
    // 1. xz = X @ win^T + b_in     (tensor core)
    mma_gemm(bufIn, p[0], p[1], bf.XZ, 2 * D, D, 0);
    // 2. conv + silu
    conv_silu_k<<<dim3(D / 128, LL, BB), 128>>>(bf.XZ, p[2], p[3], bf.Conv, D);
    // 3. xdbl = xc @ wx^T (thin; SIMT)
    gemm_k<128, 32, 16, 8, 2, 0, true>
        <<<dim3(1, MM / 128), 256>>>(bf.Conv, p[4], nullptr, bf.DBC, MM, R + 4, D, LDDBC);
    // 4-6. chunked scan
    if (R == 9)
        scanA_k<9><<<dim3(NCH, BB), D>>>(bf.DBC, bf.Conv, p[5], p[6], p[7], bf.Y, bf.S, bf.chF, bf.chS, D);
    else
        scanA_k<17><<<dim3(NCH, BB), D>>>(bf.DBC, bf.Conv, p[5], p[6], p[7], bf.Y, bf.S, bf.chF, bf.chS, D);
    scanB_k<<<(BB * D * 2 + 255) / 256, 256>>>(bf.chF, bf.chS, p[7], bf.hin, D);
    scanC_k<<<dim3(NCH, BB), D>>>(bf.DBC, bf.Conv, bf.XZ, bf.hin, p[7], p[8], bf.S, bf.Y, D, R);
    // 7. out = y @ wout^T          (tensor core)
    mma_gemm(bf.Y, p[9], nullptr, bf.MO, D, D, 0);
    // 8. layernorm
    ln_k<<<MM, D>>>(bf.MO, p[10], p[11], bf.LN, D);
}

extern "C" void kernel_launch(void* const* d_in, const int* in_sizes, int n_in,
                              void* d_out, int out_size) {
    const float* x     = (const float*)d_in[0];
    const float* lin_w = (const float*)d_in[1];
    const float* lin_b = (const float*)d_in[2];
    const float* p1[12];
    const float* p2[12];
    for (int i = 0; i < 12; i++) p1[i] = (const float*)d_in[3 + i];
    for (int i = 0; i < 12; i++) p2[i] = (const float*)d_in[15 + i];
    float* out = (float*)d_out;

    cudaFuncSetAttribute(mma_gemm_k, cudaFuncAttributeMaxDynamicSharedMemorySize, GSM_TOTAL);

    Bufs bf;
    void* p;
    cudaGetSymbolAddress(&p, g_bufA);    bf.A    = (float*)p;
    cudaGetSymbolAddress(&p, g_bufXZ);   bf.XZ   = (float*)p;
    cudaGetSymbolAddress(&p, g_bufConv); bf.Conv = (float*)p;
    cudaGetSymbolAddress(&p, g_bufDBC);  bf.DBC  = (float*)p;
    cudaGetSymbolAddress(&p, g_bufS);    bf.S    = (float*)p;
    cudaGetSymbolAddress(&p, g_bufY);    bf.Y    = (float*)p;
    cudaGetSymbolAddress(&p, g_bufMO);   bf.MO   = (float*)p;
    cudaGetSymbolAddress(&p, g_bufLN);   bf.LN   = (float*)p;
    cudaGetSymbolAddress(&p, g_chunkF);  bf.chF  = (float*)p;
    cudaGetSymbolAddress(&p, g_chunkS);  bf.chS  = (float*)p;
    cudaGetSymbolAddress(&p, g_hinit);   bf.hin  = (float*)p;

    // Input transpose: x (8,128,4096) -> t (32768,128)
    transpose_in_k<<<dim3(LL / 32, 128 / 32, BB), dim3(32, 8)>>>(x, bf.A, 128);

    // Stage 1 (d=128, r=9)
    run_stage(p1, bf.A, 128, 9, bf);

    // Inter-stage linear + silu: (M,128)@(256,128)^T (tensor core)
    mma_gemm(bf.LN, lin_w, lin_b, bf.A, 256, 128, 1);

    // Stage 2 (d=256, r=17)
    run_stage(p2, bf.A, 256, 17, bf);

    // Output transpose: t (32768,256) -> out (8,256,4096)
    transpose_out_k<<<dim3(LL / 32, 256 / 32, BB), dim3(32, 8)>>>(bf.LN, out, 256);
}

// round 6
// speedup vs baseline: 1.3909x; 1.0066x over previous
#include <cuda_runtime.h>
#include <cuda_bf16.h>
#include <cstdint>
#include <cstdio>

// ----------------------------------------------------------------------------
// Problem constants
// ----------------------------------------------------------------------------
constexpr int BB    = 8;
constexpr int LL    = 4096;
constexpr int MM    = BB * LL;        // 32768 rows
constexpr int CHUNK = 64;
constexpr int NCH   = LL / CHUNK;     // 64 chunks per batch
constexpr int LDDBC = 24;             // padded leading dim for xdbl (r+2n <= 21)
constexpr float LN_EPS = 1e-5f;

// ----------------------------------------------------------------------------
// Static scratch (device globals: sanctioned alternative to cudaMalloc)
// ----------------------------------------------------------------------------
__device__ float g_bufA   [MM * 256];        // stage input activations
__device__ float g_bufXZ  [MM * 512];        // xz = [xc | z]
__device__ float g_bufConv[MM * 256];        // silu(conv(xc))
__device__ float g_bufDBC [MM * LDDBC];      // xdbl rows
__device__ float g_bufS   [MM * 256];        // per-step cumulative dt
__device__ float g_bufY   [MM * 256];        // scan output y
__device__ float g_bufMO  [MM * 256];        // mamba output (LN input)
__device__ float g_bufLN  [MM * 256];        // LN output
__device__ float g_chunkF [BB * NCH * 256 * 2];
__device__ float g_chunkS [BB * NCH * 256];
__device__ float g_hinit  [BB * NCH * 256 * 2];

// ----------------------------------------------------------------------------
// Helpers
// ----------------------------------------------------------------------------
__device__ __forceinline__ float silu_f(float v) {
    return v / (1.f + expf(-v));
}
__device__ __forceinline__ float softplus_f(float v) {
    return (v > 20.f) ? v : log1pf(expf(v));
}

__device__ __forceinline__ uint32_t smem_to_u32(const void* smem_ptr) {
    uint32_t addr;
    asm("{ .reg .u64 tmp; cvta.to.shared.u64 tmp, %1; cvt.u32.u64 %0, tmp; }"
        : "=r"(addr) : "l"(smem_ptr));
    return addr;
}

// ldmatrix x4 (four 8x8 b16 matrices)
__device__ __forceinline__ void ldsm4(uint32_t* r, uint32_t addr) {
    asm volatile("ldmatrix.sync.aligned.m8n8.x4.shared.b16 {%0,%1,%2,%3}, [%4];"
        : "=r"(r[0]), "=r"(r[1]), "=r"(r[2]), "=r"(r[3]) : "r"(addr));
}

// D += A * B  (m16n8k16, bf16 in, fp32 acc)
__device__ __forceinline__ void mma16816(float* c, const uint32_t* a,
                                         uint32_t b0, uint32_t b1) {
    asm volatile(
        "mma.sync.aligned.m16n8k16.row.col.f32.bf16.bf16.f32 "
        "{%0,%1,%2,%3}, {%4,%5,%6,%7}, {%8,%9}, {%0,%1,%2,%3};"
        : "+f"(c[0]), "+f"(c[1]), "+f"(c[2]), "+f"(c[3])
        : "r"(a[0]), "r"(a[1]), "r"(a[2]), "r"(a[3]), "r"(b0), "r"(b1));
}

// ----------------------------------------------------------------------------
// Tensor-core GEMM via mma.sync: C[M,N] = A[M,K] @ W[N,K]^T (+bias) (epi 1=silu)
// fp32 I/O; bf16 hi/lo 3-term split internally (residual ~2^-16).
// CTA: 256 threads (8 warps, 2x4), tile 128x128, BK=32, double-buffered smem.
// MMA issue is TERM-MAJOR: all 16 accumulators are touched per term, so the
// same-accumulator reuse distance is 48 MMAs (no latency serialization).
// ----------------------------------------------------------------------------
constexpr int GSM_STAGE = 32768;               // Ah(8K)+Al(8K)+Bh(8K)+Bl(8K)
constexpr int GSM_TOTAL = 2 * GSM_STAGE;       // double buffer

__global__ __launch_bounds__(256) void mma_gemm_k(
    const float* __restrict__ A, const float* __restrict__ W,
    const float* __restrict__ bias, float* __restrict__ C,
    int Nn, int Kk, int epi) {
    extern __shared__ char smem[];
    const uint32_t sb = smem_to_u32(smem);
    const int tid  = threadIdx.x;
    const int lane = tid & 31;
    const int w    = tid >> 5;
    const int wm   = w >> 2;          // 0..1
    const int wn   = w & 3;           // 0..3
    const int m0 = blockIdx.y * 128;
    const int n0 = blockIdx.x * 128;

    // ldmatrix per-thread addressing
    const int g  = lane >> 3;         // matrix id 0..3
    const int lr = lane & 7;
    const int gk = g >> 1;            // k-chunk offset contributed by matrix id
    const int arow = wm * 64 + lr + ((g & 1) << 3);
    const int brow = wn * 32 + lr + ((g & 1) << 3);
    const int s_a = (arow >> 1) & 3;
    const int s_b = (brow >> 1) & 3;
    const uint32_t aoff = sb + (uint32_t)arow * 64;           // into Ah
    const uint32_t boff = sb + 16384u + (uint32_t)brow * 64;  // into Bh

    float acc[4][4][4];
    #pragma unroll
    for (int i = 0; i < 4; i++)
        #pragma unroll
        for (int j = 0; j < 4; j++)
            #pragma unroll
            for (int q = 0; q < 4; q++) acc[i][j][q] = 0.f;

    const int nch = Kk >> 5;
    float2 pfA[8], pfB[8];

    // prologue: fetch + stage chunk 0
    {
        #pragma unroll
        for (int i = 0; i < 8; i++) {
            int p = tid + (i << 8);
            int row = p >> 4, pc = p & 15;
            pfA[i] = *reinterpret_cast<const float2*>(A + (size_t)(m0 + row) * Kk + pc * 2);
            pfB[i] = *reinterpret_cast<const float2*>(W + (size_t)(n0 + row) * Kk + pc * 2);
        }
        #pragma unroll
        for (int i = 0; i < 8; i++) {
            int p = tid + (i << 8);
            int row = p >> 4, pc = p & 15;
            uint32_t off = (uint32_t)(row * 64 + (((pc >> 2) ^ ((row >> 1) & 3)) << 4) + (pc & 3) * 4);
            float2 va = pfA[i];
            __nv_bfloat162 ha = __floats2bfloat162_rn(va.x, va.y);
            __nv_bfloat162 la = __floats2bfloat162_rn(va.x - __bfloat162float(ha.x),
                                                      va.y - __bfloat162float(ha.y));
            *reinterpret_cast<uint32_t*>(smem + off)         = *reinterpret_cast<uint32_t*>(&ha);
            *reinterpret_cast<uint32_t*>(smem + 8192 + off)  = *reinterpret_cast<uint32_t*>(&la);
            float2 vb = pfB[i];
            __nv_bfloat162 hb = __floats2bfloat162_rn(vb.x, vb.y);
            __nv_bfloat162 lb = __floats2bfloat162_rn(vb.x - __bfloat162float(hb.x),
                                                      vb.y - __bfloat162float(hb.y));
            *reinterpret_cast<uint32_t*>(smem + 16384 + off) = *reinterpret_cast<uint32_t*>(&hb);
            *reinterpret_cast<uint32_t*>(smem + 24576 + off) = *reinterpret_cast<uint32_t*>(&lb);
        }
    }

    for (int c = 0; c < nch; c++) {
        __syncthreads();
        // prefetch next chunk into registers (overlaps with MMA below)
        if (c + 1 < nch) {
            const int k0 = (c + 1) << 5;
            #pragma unroll
            for (int i = 0; i < 8; i++) {
                int p = tid + (i << 8);
                int row = p >> 4, pc = p & 15;
                pfA[i] = *reinterpret_cast<const float2*>(A + (size_t)(m0 + row) * Kk + k0 + pc * 2);
                pfB[i] = *reinterpret_cast<const float2*>(W + (size_t)(n0 + row) * Kk + k0 + pc * 2);
            }
        }
        // compute on buffer c&1
        const uint32_t sA = aoff + (uint32_t)(c & 1) * GSM_STAGE;
        const uint32_t sB = boff + (uint32_t)(c & 1) * GSM_STAGE;
        #pragma unroll
        for (int ks = 0; ks < 2; ks++) {
            const uint32_t coA = (uint32_t)((((ks << 1) + gk) ^ s_a) << 4);
            const uint32_t coB = (uint32_t)((((ks << 1) + gk) ^ s_b) << 4);
            uint32_t aH[4][4], aL[4][4], bH[2][4], bL[2][4];
            #pragma unroll
            for (int np = 0; np < 2; np++) {
                ldsm4(bH[np], sB + np * 1024 + coB);
                ldsm4(bL[np], sB + 8192 + np * 1024 + coB);
            }
            #pragma unroll
            for (int mi = 0; mi < 4; mi++) {
                ldsm4(aH[mi], sA + mi * 1024 + coA);
                ldsm4(aL[mi], sA + 8192 + mi * 1024 + coA);
            }
            // term 1: Ah * Bh  (16 independent accumulators)
            #pragma unroll
            for (int mi = 0; mi < 4; mi++)
                #pragma unroll
                for (int ni = 0; ni < 4; ni++) {
                    const int np = ni >> 1, sel = ni & 1;
                    mma16816(acc[mi][ni], aH[mi], bH[np][sel], bH[np][sel + 2]);
                }
            // term 2: Al * Bh
            #pragma unroll
            for (int mi = 0; mi < 4; mi++)
                #pragma unroll
                for (int ni = 0; ni < 4; ni++) {
                    const int np = ni >> 1, sel = ni & 1;
                    mma16816(acc[mi][ni], aL[mi], bH[np][sel], bH[np][sel + 2]);
                }
            // term 3: Ah * Bl
            #pragma unroll
            for (int mi = 0; mi < 4; mi++)
                #pragma unroll
                for (int ni = 0; ni < 4; ni++) {
                    const int np = ni >> 1, sel = ni & 1;
                    mma16816(acc[mi][ni], aH[mi], bL[np][sel], bL[np][sel + 2]);
                }
        }
        // stage next chunk (targets buffer (c+1)&1, last read in iter c-1: safe)
        if (c + 1 < nch) {
            char* dst = smem + ((c + 1) & 1) * GSM_STAGE;
            #pragma unroll
            for (int i = 0; i < 8; i++) {
                int p = tid + (i << 8);
                int row = p >> 4, pc = p & 15;
                uint32_t off = (uint32_t)(row * 64 + (((pc >> 2) ^ ((row >> 1) & 3)) << 4) + (pc & 3) * 4);
                float2 va = pfA[i];
                __nv_bfloat162 ha = __floats2bfloat162_rn(va.x, va.y);
                __nv_bfloat162 la = __floats2bfloat162_rn(va.x - __bfloat162float(ha.x),
                                                          va.y - __bfloat162float(ha.y));
                *reinterpret_cast<uint32_t*>(dst + off)         = *reinterpret_cast<uint32_t*>(&ha);
                *reinterpret_cast<uint32_t*>(dst + 8192 + off)  = *reinterpret_cast<uint32_t*>(&la);
                float2 vb = pfB[i];
                __nv_bfloat162 hb = __floats2bfloat162_rn(vb.x, vb.y);
                __nv_bfloat162 lb = __floats2bfloat162_rn(vb.x - __bfloat162float(hb.x),
                                                          vb.y - __bfloat162float(hb.y));
                *reinterpret_cast<uint32_t*>(dst + 16384 + off) = *reinterpret_cast<uint32_t*>(&hb);
                *reinterpret_cast<uint32_t*>(dst + 24576 + off) = *reinterpret_cast<uint32_t*>(&lb);
            }
        }
    }

    // epilogue: bias (+silu) and store, float2 per (mi, ni, half)
    #pragma unroll
    for (int mi = 0; mi < 4; mi++) {
        #pragma unroll
        for (int ni = 0; ni < 4; ni++) {
            const int gr = m0 + wm * 64 + mi * 16 + (lane >> 2);
            const int gc = n0 + wn * 32 + ni * 8 + (lane & 3) * 2;
            float b0 = 0.f, b1 = 0.f;
            if (bias) { b0 = bias[gc]; b1 = bias[gc + 1]; }
            float v0 = acc[mi][ni][0] + b0, v1 = acc[mi][ni][1] + b1;
            float v2 = acc[mi][ni][2] + b0, v3 = acc[mi][ni][3] + b1;
            if (epi == 1) { v0 = silu_f(v0); v1 = silu_f(v1); v2 = silu_f(v2); v3 = silu_f(v3); }
            float2 lo; lo.x = v0; lo.y = v1;
            float2 hi; hi.x = v2; hi.y = v3;
            *reinterpret_cast<float2*>(&C[(size_t)gr * Nn + gc])       = lo;
            *reinterpret_cast<float2*>(&C[(size_t)(gr + 8) * Nn + gc]) = hi;
        }
    }
}

// ----------------------------------------------------------------------------
// Transposes: x (b, C, L) <-> t (b, L, C)
// ----------------------------------------------------------------------------
__global__ void transpose_in_k(const float* __restrict__ x, float* __restrict__ t, int Cc) {
    __shared__ float tile[32][33];
    int b  = blockIdx.z;
    int l0 = blockIdx.x * 32;
    int c0 = blockIdx.y * 32;
    int tx = threadIdx.x, ty = threadIdx.y;
    #pragma unroll
    for (int i = 0; i < 32; i += 8)
        tile[ty + i][tx] = x[((size_t)b * Cc + c0 + ty + i) * LL + l0 + tx];
    __syncthreads();
    #pragma unroll
    for (int i = 0; i < 32; i += 8)
        t[((size_t)b * LL + l0 + ty + i) * Cc + c0 + tx] = tile[tx][ty + i];
}

__global__ void transpose_out_k(const float* __restrict__ t, float* __restrict__ o, int Cc) {
    __shared__ float tile[32][33];
    int b  = blockIdx.z;
    int l0 = blockIdx.x * 32;
    int c0 = blockIdx.y * 32;
    int tx = threadIdx.x, ty = threadIdx.y;
    #pragma unroll
    for (int i = 0; i < 32; i += 8)
        tile[ty + i][tx] = t[((size_t)b * LL + l0 + ty + i) * Cc + c0 + tx];
    __syncthreads();
    #pragma unroll
    for (int i = 0; i < 32; i += 8)
        o[((size_t)b * Cc + c0 + ty + i) * LL + l0 + tx] = tile[tx][ty + i];
}

// ----------------------------------------------------------------------------
// SIMT fp32 GEMM (kept for the thin xdbl projection only)
// ----------------------------------------------------------------------------
template <int BM, int BN, int BK, int TM, int TN, int EPI, bool NGUARD>
__global__ __launch_bounds__((BM / TM) * (BN / TN))
void gemm_k(const float* __restrict__ A, const float* __restrict__ W,
            const float* __restrict__ bias, float* __restrict__ C,
            int Mm, int Nn, int Kk, int ldc) {
    constexpr int THREADS = (BM / TM) * (BN / TN);
    constexpr int KV = BK / 4;
    __shared__ float As[BK][BM];
    __shared__ float Bs[BK][BN];
    const int tid  = threadIdx.x;
    const int m0   = blockIdx.y * BM;
    const int n0   = blockIdx.x * BN;
    const int tcol = tid % (BN / TN);
    const int trow = tid / (BN / TN);
    float acc[TM][TN];
    #pragma unroll
    for (int i = 0; i < TM; i++)
        #pragma unroll
        for (int j = 0; j < TN; j++) acc[i][j] = 0.f;

    for (int k0 = 0; k0 < Kk; k0 += BK) {
        #pragma unroll
        for (int idx = tid; idx < BM * KV; idx += THREADS) {
            int am = idx / KV, ak = idx % KV;
            float4 v = *reinterpret_cast<const float4*>(A + (size_t)(m0 + am) * Kk + k0 + ak * 4);
            As[ak * 4 + 0][am] = v.x; As[ak * 4 + 1][am] = v.y;
            As[ak * 4 + 2][am] = v.z; As[ak * 4 + 3][am] = v.w;
        }
        #pragma unroll
        for (int idx = tid; idx < BN * KV; idx += THREADS) {
            int bn = idx / KV, bk = idx % KV;
            float4 v = make_float4(0.f, 0.f, 0.f, 0.f);
            if (!NGUARD || (n0 + bn) < Nn)
                v = *reinterpret_cast<const float4*>(W + (size_t)(n0 + bn) * Kk + k0 + bk * 4);
            Bs[bk * 4 + 0][bn] = v.x; Bs[bk * 4 + 1][bn] = v.y;
            Bs[bk * 4 + 2][bn] = v.z; Bs[bk * 4 + 3][bn] = v.w;
        }
        __syncthreads();
        #pragma unroll
        for (int k = 0; k < BK; k++) {
            float ra[TM], rb[TN];
            #pragma unroll
            for (int i = 0; i < TM; i++) ra[i] = As[k][trow * TM + i];
            #pragma unroll
            for (int j = 0; j < TN; j++) rb[j] = Bs[k][tcol * TN + j];
            #pragma unroll
            for (int i = 0; i < TM; i++)
                #pragma unroll
                for (int j = 0; j < TN; j++) acc[i][j] += ra[i] * rb[j];
        }
        __syncthreads();
    }

    #pragma unroll
    for (int i = 0; i < TM; i++) {
        int m = m0 + trow * TM + i;
        #pragma unroll
        for (int j = 0; j < TN; j++) {
            int n = n0 + tcol * TN + j;
            if (NGUARD && n >= Nn) continue;
            float v = acc[i][j];
            if (bias) v += bias[n];
            if (EPI == 1) v = silu_f(v);
            C[(size_t)m * ldc + n] = v;
        }
    }
}

// ----------------------------------------------------------------------------
// Causal depthwise conv (k=4, pad (3,0)) + bias + silu.
// ----------------------------------------------------------------------------
__global__ void conv_silu_k(const float* __restrict__ xz, const float* __restrict__ cw,
                            const float* __restrict__ cb, float* __restrict__ out, int D) {
    int d = blockIdx.x * blockDim.x + threadIdx.x;
    int l = blockIdx.y, b = blockIdx.z;
    if (d >= D) return;
    int ld = 2 * D;
    size_t rowb = (size_t)b * LL + l;
    float w0 = cw[d * 4], w1 = cw[d * 4 + 1], w2 = cw[d * 4 + 2], w3 = cw[d * 4 + 3];
    float acc = cb[d];
    if (l >= 3) acc += xz[(rowb - 3) * ld + d] * w0;
    if (l >= 2) acc += xz[(rowb - 2) * ld + d] * w1;
    if (l >= 1) acc += xz[(rowb - 1) * ld + d] * w2;
    acc += xz[rowb * ld + d] * w3;
    out[rowb * D + d] = silu_f(acc);
}

// ----------------------------------------------------------------------------
// Chunked parallel scan (phases A, B, C)
// ----------------------------------------------------------------------------
template <int R>
__global__ void scanA_k(const float* __restrict__ dbc, const float* __restrict__ conv,
                        const float* __restrict__ wdt, const float* __restrict__ bdt,
                        const float* __restrict__ alog,
                        float* __restrict__ ybuf, float* __restrict__ sbuf,
                        float* __restrict__ chF, float* __restrict__ chS, int D) {
    __shared__ float sh[CHUNK * LDDBC];
    int d = threadIdx.x, ch = blockIdx.x, b = blockIdx.y;
    size_t lbase = (size_t)b * LL + ch * CHUNK;
    for (int idx = d; idx < CHUNK * LDDBC; idx += D)
        sh[idx] = dbc[lbase * LDDBC + idx];
    float wr[R];
    #pragma unroll
    for (int q = 0; q < R; q++) wr[q] = wdt[d * R + q];
    float A0 = -expf(alog[d * 2 + 0]);
    float A1 = -expf(alog[d * 2 + 1]);
    float bd = bdt[d];
    float h0 = 0.f, h1 = 0.f, S = 0.f;
    __syncthreads();
    for (int t0 = 0; t0 < CHUNK; t0 += 8) {
        float xcv[8];
        #pragma unroll
        for (int i = 0; i < 8; i++) xcv[i] = conv[(lbase + t0 + i) * D + d];
        #pragma unroll
        for (int i = 0; i < 8; i++) {
            const float* row = &sh[(t0 + i) * LDDBC];
            float dtr = bd;
            #pragma unroll
            for (int q = 0; q < R; q++) dtr += wr[q] * row[q];
            float dt = softplus_f(dtr);
            S += dt;
            float u = dt * xcv[i];
            h0 = expf(dt * A0) * h0 + u * row[R];
            h1 = expf(dt * A1) * h1 + u * row[R + 1];
            ybuf[(lbase + t0 + i) * D + d] = h0 * row[R + 2] + h1 * row[R + 3];
            sbuf[(lbase + t0 + i) * D + d] = S;
        }
    }
    size_t ci = ((size_t)(b * NCH + ch)) * D + d;
    chF[ci * 2 + 0] = h0;
    chF[ci * 2 + 1] = h1;
    chS[ci] = S;
}

__global__ void scanB_k(const float* __restrict__ chF, const float* __restrict__ chS,
                        const float* __restrict__ alog, float* __restrict__ hinit, int D) {
    int idx = blockIdx.x * blockDim.x + threadIdx.x;
    if (idx >= BB * D * 2) return;
    int j = idx & 1;
    int d = (idx >> 1) % D;
    int b = idx / (2 * D);
    float A = -expf(alog[d * 2 + j]);
    float H = 0.f;
    for (int ch = 0; ch < NCH; ch++) {
        size_t ci = ((size_t)(b * NCH + ch)) * D + d;
        hinit[ci * 2 + j] = H;
        H = expf(A * chS[ci]) * H + chF[ci * 2 + j];
    }
}

__global__ void scanC_k(const float* __restrict__ dbc, const float* __restrict__ conv,
                        const float* __restrict__ xz, const float* __restrict__ hinit,
                        const float* __restrict__ alog, const float* __restrict__ dd,
                        const float* __restrict__ sbuf, float* __restrict__ ybuf,
                        int D, int r) {
    __shared__ float sh[CHUNK * LDDBC];
    int d = threadIdx.x, ch = blockIdx.x, b = blockIdx.y;
    size_t lbase = (size_t)b * LL + ch * CHUNK;
    for (int idx = d; idx < CHUNK * LDDBC; idx += D)
        sh[idx] = dbc[lbase * LDDBC + idx];
    float A0 = -expf(alog[d * 2 + 0]);
    float A1 = -expf(alog[d * 2 + 1]);
    size_t ci = ((size_t)(b * NCH + ch)) * D + d;
    float h00 = hinit[ci * 2 + 0], h01 = hinit[ci * 2 + 1];
    float ddv = dd[d];
    int ld2 = 2 * D;
    __syncthreads();
    for (int t0 = 0; t0 < CHUNK; t0 += 8) {
        float xcv[8], zv[8], Sv[8], ylv[8];
        #pragma unroll
        for (int i = 0; i < 8; i++) {
            size_t rb = lbase + t0 + i;
            xcv[i] = conv[rb * D + d];
            zv[i]  = xz[rb * ld2 + D + d];
            Sv[i]  = sbuf[rb * D + d];
            ylv[i] = ybuf[rb * D + d];
        }
        #pragma unroll
        for (int i = 0; i < 8; i++) {
            const float* row = &sh[(t0 + i) * LDDBC];
            float y = ylv[i]
                    + expf(A0 * Sv[i]) * h00 * row[r + 2]
                    + expf(A1 * Sv[i]) * h01 * row[r + 3]
                    + ddv * xcv[i];
            y *= silu_f(zv[i]);
            ybuf[(lbase + t0 + i) * D + d] = y;
        }
    }
}

// ----------------------------------------------------------------------------
// LayerNorm over last dim (block per row, D threads)
// ----------------------------------------------------------------------------
__global__ void ln_k(const float* __restrict__ in, const float* __restrict__ w,
                     const float* __restrict__ bgm, float* __restrict__ out, int D) {
    int m = blockIdx.x, d = threadIdx.x;
    float v = in[(size_t)m * D + d];
    float s = v, sq = v * v;
    #pragma unroll
    for (int o = 16; o > 0; o >>= 1) {
        s  += __shfl_xor_sync(0xffffffffu, s,  o);
        sq += __shfl_xor_sync(0xffffffffu, sq, o);
    }
    __shared__ float ws[8], wq[8];
    __shared__ float mu_s, rstd_s;
    int warp = d >> 5, lane = d & 31, nw = D >> 5;
    if (lane == 0) { ws[warp] = s; wq[warp] = sq; }
    __syncthreads();
    if (d == 0) {
        float ts = 0.f, tq = 0.f;
        for (int i = 0; i < nw; i++) { ts += ws[i]; tq += wq[i]; }
        float mu  = ts / D;
        float var = tq / D - mu * mu;
        mu_s = mu;
        rstd_s = rsqrtf(var + LN_EPS);
    }
    __syncthreads();
    out[(size_t)m * D + d] = (v - mu_s) * rstd_s * w[d] + bgm[d];
}

// ----------------------------------------------------------------------------
// Host-side driver
// ----------------------------------------------------------------------------
struct Bufs {
    float *A, *XZ, *Conv, *DBC, *S, *Y, *MO, *LN, *chF, *chS, *hin;
};

static void mma_gemm(const float* A, const float* W, const float* bias, float* C,
                     int N, int K, int epi) {
    mma_gemm_k<<<dim3(N / 128, MM / 128), 256, GSM_TOTAL>>>(A, W, bias, C, N, K, epi);
}

static void run_stage(const float* const* p, const float* bufIn, int D, int R, const Bufs& bf) {
    // 1. xz = X @ win^T + b_in     (tensor core)
    mma_gemm(bufIn, p[0], p[1], bf.XZ, 2 * D, D, 0);
    // 2. conv + silu
    conv_silu_k<<<dim3(D / 128, LL, BB), 128>>>(bf.XZ, p[2], p[3], bf.Conv, D);
    // 3. xdbl = xc @ wx^T (thin; SIMT)
    gemm_k<128, 32, 16, 8, 2, 0, true>
        <<<dim3(1, MM / 128), 256>>>(bf.Conv, p[4], nullptr, bf.DBC, MM, R + 4, D, LDDBC);
    // 4-6. chunked scan
    if (R == 9)
        scanA_k<9><<<dim3(NCH, BB), D>>>(bf.DBC, bf.Conv, p[5], p[6], p[7], bf.Y, bf.S, bf.chF, bf.chS, D);
    else
        scanA_k<17><<<dim3(NCH, BB), D>>>(bf.DBC, bf.Conv, p[5], p[6], p[7], bf.Y, bf.S, bf.chF, bf.chS, D);
    scanB_k<<<(BB * D * 2 + 255) / 256, 256>>>(bf.chF, bf.chS, p[7], bf.hin, D);
    scanC_k<<<dim3(NCH, BB), D>>>(bf.DBC, bf.Conv, bf.XZ, bf.hin, p[7], p[8], bf.S, bf.Y, D, R);
    // 7. out = y @ wout^T          (tensor core)
    mma_gemm(bf.Y, p[9], nullptr, bf.MO, D, D, 0);
    // 8. layernorm
    ln_k<<<MM, D>>>(bf.MO, p[10], p[11], bf.LN, D);
}

extern "C" void kernel_launch(void* const* d_in, const int* in_sizes, int n_in,
                              void* d_out, int out_size) {
    const float* x     = (const float*)d_in[0];
    const float* lin_w = (const float*)d_in[1];
    const float* lin_b = (const float*)d_in[2];
    const float* p1[12];
    const float* p2[12];
    for (int i = 0; i < 12; i++) p1[i] = (const float*)d_in[3 + i];
    for (int i = 0; i < 12; i++) p2[i] = (const float*)d_in[15 + i];
    float* out = (float*)d_out;

    cudaFuncSetAttribute(mma_gemm_k, cudaFuncAttributeMaxDynamicSharedMemorySize, GSM_TOTAL);

    Bufs bf;
    void* p;
    cudaGetSymbolAddress(&p, g_bufA);    bf.A    = (float*)p;
    cudaGetSymbolAddress(&p, g_bufXZ);   bf.XZ   = (float*)p;
    cudaGetSymbolAddress(&p, g_bufConv); bf.Conv = (float*)p;
    cudaGetSymbolAddress(&p, g_bufDBC);  bf.DBC  = (float*)p;
    cudaGetSymbolAddress(&p, g_bufS);    bf.S    = (float*)p;
    cudaGetSymbolAddress(&p, g_bufY);    bf.Y    = (float*)p;
    cudaGetSymbolAddress(&p, g_bufMO);   bf.MO   = (float*)p;
    cudaGetSymbolAddress(&p, g_bufLN);   bf.LN   = (float*)p;
    cudaGetSymbolAddress(&p, g_chunkF);  bf.chF  = (float*)p;
    cudaGetSymbolAddress(&p, g_chunkS);  bf.chS  = (float*)p;
    cudaGetSymbolAddress(&p, g_hinit);   bf.hin  = (float*)p;

    // Input transpose: x (8,128,4096) -> t (32768,128)
    transpose_in_k<<<dim3(LL / 32, 128 / 32, BB), dim3(32, 8)>>>(x, bf.A, 128);

    // Stage 1 (d=128, r=9)
    run_stage(p1, bf.A, 128, 9, bf);

    // Inter-stage linear + silu: (M,128)@(256,128)^T (tensor core)
    mma_gemm(bf.LN, lin_w, lin_b, bf.A, 256, 128, 1);

    // Stage 2 (d=256, r=17)
    run_stage(p2, bf.A, 256, 17, bf);

    // Output transpose: t (32768,256) -> out (8,256,4096)
    transpose_out_k<<<dim3(LL / 32, 256 / 32, BB), dim3(32, 8)>>>(bf.LN, out, 256);
}

// round 7
// speedup vs baseline: 1.4148x; 1.0171x over previous
#include <cuda_runtime.h>
#include <cuda_bf16.h>
#include <cstdint>
#include <cstdio>

// ----------------------------------------------------------------------------
// Problem constants
// ----------------------------------------------------------------------------
constexpr int BB    = 8;
constexpr int LL    = 4096;
constexpr int MM    = BB * LL;        // 32768 rows
constexpr int CHUNK = 64;
constexpr int NCH   = LL / CHUNK;     // 64 chunks per batch
constexpr int LDDBC = 24;             // padded leading dim for xdbl (r+2n <= 21)
constexpr float LN_EPS = 1e-5f;

// ----------------------------------------------------------------------------
// Static scratch (device globals)
// ----------------------------------------------------------------------------
__device__ float g_bufXZ  [MM * 512];        // xz = [xc | z] (fp32)
__device__ float g_bufConv[MM * 256];        // silu(conv(xc)) (fp32)
__device__ float g_bufDBC [MM * LDDBC];      // xdbl rows (fp32)
__device__ float g_bufMO  [MM * 256];        // mamba output (LN input)
__device__ float g_bufLN  [MM * 256];        // LN output fp32 (stage-2 only)
__device__ float g_chunkF [BB * NCH * 256 * 2];
__device__ float g_chunkS [BB * NCH * 256];
__device__ float g_hinit  [BB * NCH * 256 * 2];
// bf16 hi/lo operand buffers for tensor-core GEMMs
__device__ __nv_bfloat16 g_Ah [MM * 256];    // stage input act (s1: transpose, s2: lin out)
__device__ __nv_bfloat16 g_Al [MM * 256];
__device__ __nv_bfloat16 g_LNh[MM * 128];    // s1 LN output
__device__ __nv_bfloat16 g_LNl[MM * 128];
__device__ __nv_bfloat16 g_Yh [MM * 256];    // scan output
__device__ __nv_bfloat16 g_Yl [MM * 256];
constexpr int WTOT = 278528;                 // win1+wout1+lin+win2+wout2
__device__ __nv_bfloat16 g_Wh [WTOT];
__device__ __nv_bfloat16 g_Wl [WTOT];

// ----------------------------------------------------------------------------
// Helpers
// ----------------------------------------------------------------------------
__device__ __forceinline__ float silu_f(float v) { return v / (1.f + expf(-v)); }
__device__ __forceinline__ float softplus_f(float v) {
    return (v > 20.f) ? v : log1pf(expf(v));
}

__device__ __forceinline__ uint32_t smem_to_u32(const void* smem_ptr) {
    uint32_t addr;
    asm("{ .reg .u64 tmp; cvta.to.shared.u64 tmp, %1; cvt.u32.u64 %0, tmp; }"
        : "=r"(addr) : "l"(smem_ptr));
    return addr;
}

__device__ __forceinline__ void ldsm4(uint32_t* r, uint32_t addr) {
    asm volatile("ldmatrix.sync.aligned.m8n8.x4.shared.b16 {%0,%1,%2,%3}, [%4];"
        : "=r"(r[0]), "=r"(r[1]), "=r"(r[2]), "=r"(r[3]) : "r"(addr));
}

__device__ __forceinline__ void mma16816(float* c, const uint32_t* a,
                                         uint32_t b0, uint32_t b1) {
    asm volatile(
        "mma.sync.aligned.m16n8k16.row.col.f32.bf16.bf16.f32 "
        "{%0,%1,%2,%3}, {%4,%5,%6,%7}, {%8,%9}, {%0,%1,%2,%3};"
        : "+f"(c[0]), "+f"(c[1]), "+f"(c[2]), "+f"(c[3])
        : "r"(a[0]), "r"(a[1]), "r"(a[2]), "r"(a[3]), "r"(b0), "r"(b1));
}

__device__ __forceinline__ void cp16(uint32_t dst, const void* src) {
    asm volatile("cp.async.ca.shared.global [%0], [%1], 16;"
        :: "r"(dst), "l"(__cvta_generic_to_global(src)) : "memory");
}
#define CP_COMMIT() asm volatile("cp.async.commit_group;" ::: "memory")

// hi/lo bf16 split of a float pair, packed as bf16x2 words
__device__ __forceinline__ void pack_hl(float a, float b, uint32_t& hi, uint32_t& lo) {
    __nv_bfloat162 h = __floats2bfloat162_rn(a, b);
    __nv_bfloat162 l = __floats2bfloat162_rn(a - __bfloat162float(h.x),
                                             b - __bfloat162float(h.y));
    hi = *reinterpret_cast<uint32_t*>(&h);
    lo = *reinterpret_cast<uint32_t*>(&l);
}

// ----------------------------------------------------------------------------
// Tensor-core GEMM, pre-split bf16 operands:
//   C[M,N] = (Ah+Al)[M,K] @ (Wh+Wl)[N,K]^T  (3-term split, fp32 acc)
// cp.async double-buffered staging, zero conversion math in-kernel.
// Output: fp32 (Cf) or bf16 hi/lo (Ch/Cl). epi 1 = silu.
// smem layout per stage: Ah(8K) Al(8K) Bh(8K) Bl(8K); per-array
//   off(r,k) = r*64 + (((k>>3) ^ ((r>>1)&3))<<4) + (k&7)*2
// ----------------------------------------------------------------------------
constexpr int GSM_STAGE = 32768;
constexpr int GSM_TOTAL = 2 * GSM_STAGE;

__global__ __launch_bounds__(256) void mma_gemm_k(
    const __nv_bfloat16* __restrict__ Ah, const __nv_bfloat16* __restrict__ Al,
    const __nv_bfloat16* __restrict__ Wh, const __nv_bfloat16* __restrict__ Wl,
    const float* __restrict__ bias, float* __restrict__ Cf,
    __nv_bfloat16* __restrict__ Ch, __nv_bfloat16* __restrict__ Cl,
    int Nn, int Kk, int epi) {
    extern __shared__ char smem[];
    const uint32_t sb = smem_to_u32(smem);
    const int tid  = threadIdx.x;
    const int lane = tid & 31;
    const int w    = tid >> 5;
    const int wm   = w >> 2;
    const int wn   = w & 3;
    const int m0 = blockIdx.y * 128;
    const int n0 = blockIdx.x * 128;

    // ldmatrix per-thread addressing
    const int g  = lane >> 3;
    const int lr = lane & 7;
    const int gk = g >> 1;
    const int arow = wm * 64 + lr + ((g & 1) << 3);
    const int brow = wn * 32 + lr + ((g & 1) << 3);
    const int s_a = (arow >> 1) & 3;
    const int s_b = (brow >> 1) & 3;
    const uint32_t aoff = sb + (uint32_t)arow * 64;
    const uint32_t boff = sb + 16384u + (uint32_t)brow * 64;

    // cp.async per-thread addressing: 2 16B-chunks per array
    const int cid0 = tid;
    const int cid1 = tid + 256;
    const int r0 = cid0 >> 2, j0 = cid0 & 3;
    const int r1 = cid1 >> 2, j1 = cid1 & 3;
    const uint32_t so0 = (uint32_t)(r0 * 64 + ((j0 ^ ((r0 >> 1) & 3)) << 4));
    const uint32_t so1 = (uint32_t)(r1 * 64 + ((j1 ^ ((r1 >> 1) & 3)) << 4));

    float acc[4][4][4];
    #pragma unroll
    for (int i = 0; i < 4; i++)
        #pragma unroll
        for (int j = 0; j < 4; j++)
            #pragma unroll
            for (int q = 0; q < 4; q++) acc[i][j][q] = 0.f;

    const int nch = Kk >> 5;

    auto issue = [&](int c) {
        const int k0 = c << 5;
        const uint32_t sbase = sb + (uint32_t)(c & 1) * GSM_STAGE;
        cp16(sbase + so0,          Ah + (size_t)(m0 + r0) * Kk + k0 + j0 * 8);
        cp16(sbase + so1,          Ah + (size_t)(m0 + r1) * Kk + k0 + j1 * 8);
        cp16(sbase + 8192 + so0,   Al + (size_t)(m0 + r0) * Kk + k0 + j0 * 8);
        cp16(sbase + 8192 + so1,   Al + (size_t)(m0 + r1) * Kk + k0 + j1 * 8);
        cp16(sbase + 16384 + so0,  Wh + (size_t)(n0 + r0) * Kk + k0 + j0 * 8);
        cp16(sbase + 16384 + so1,  Wh + (size_t)(n0 + r1) * Kk + k0 + j1 * 8);
        cp16(sbase + 24576 + so0,  Wl + (size_t)(n0 + r0) * Kk + k0 + j0 * 8);
        cp16(sbase + 24576 + so1,  Wl + (size_t)(n0 + r1) * Kk + k0 + j1 * 8);
        CP_COMMIT();
    };

    issue(0);
    if (nch > 1) issue(1);

    for (int c = 0; c < nch; c++) {
        if (c + 1 < nch) asm volatile("cp.async.wait_group 1;" ::: "memory");
        else             asm volatile("cp.async.wait_group 0;" ::: "memory");
        __syncthreads();

        const uint32_t sA = aoff + (uint32_t)(c & 1) * GSM_STAGE;
        const uint32_t sB = boff + (uint32_t)(c & 1) * GSM_STAGE;
        #pragma unroll
        for (int ks = 0; ks < 2; ks++) {
            const uint32_t coA = (uint32_t)((((ks << 1) + gk) ^ s_a) << 4);
            const uint32_t coB = (uint32_t)((((ks << 1) + gk) ^ s_b) << 4);
            uint32_t aH[4][4], aL[4][4], bH[2][4], bL[2][4];
            #pragma unroll
            for (int np = 0; np < 2; np++) {
                ldsm4(bH[np], sB + np * 1024 + coB);
                ldsm4(bL[np], sB + 8192 + np * 1024 + coB);
            }
            #pragma unroll
            for (int mi = 0; mi < 4; mi++) {
                ldsm4(aH[mi], sA + mi * 1024 + coA);
                ldsm4(aL[mi], sA + 8192 + mi * 1024 + coA);
            }
            #pragma unroll
            for (int mi = 0; mi < 4; mi++)
                #pragma unroll
                for (int ni = 0; ni < 4; ni++) {
                    const int np = ni >> 1, sel = ni & 1;
                    mma16816(acc[mi][ni], aH[mi], bH[np][sel], bH[np][sel + 2]);
                }
            #pragma unroll
            for (int mi = 0; mi < 4; mi++)
                #pragma unroll
                for (int ni = 0; ni < 4; ni++) {
                    const int np = ni >> 1, sel = ni & 1;
                    mma16816(acc[mi][ni], aL[mi], bH[np][sel], bH[np][sel + 2]);
                }
            #pragma unroll
            for (int mi = 0; mi < 4; mi++)
                #pragma unroll
                for (int ni = 0; ni < 4; ni++) {
                    const int np = ni >> 1, sel = ni & 1;
                    mma16816(acc[mi][ni], aH[mi], bL[np][sel], bL[np][sel + 2]);
                }
        }
        __syncthreads();
        if (c + 2 < nch) issue(c + 2);
    }

    // epilogue
    #pragma unroll
    for (int mi = 0; mi < 4; mi++) {
        #pragma unroll
        for (int ni = 0; ni < 4; ni++) {
            const int gr = m0 + wm * 64 + mi * 16 + (lane >> 2);
            const int gc = n0 + wn * 32 + ni * 8 + (lane & 3) * 2;
            float b0 = 0.f, b1 = 0.f;
            if (bias) { b0 = bias[gc]; b1 = bias[gc + 1]; }
            float v0 = acc[mi][ni][0] + b0, v1 = acc[mi][ni][1] + b1;
            float v2 = acc[mi][ni][2] + b0, v3 = acc[mi][ni][3] + b1;
            if (epi == 1) { v0 = silu_f(v0); v1 = silu_f(v1); v2 = silu_f(v2); v3 = silu_f(v3); }
            if (Cf) {
                float2 lo; lo.x = v0; lo.y = v1;
                float2 hi; hi.x = v2; hi.y = v3;
                *reinterpret_cast<float2*>(&Cf[(size_t)gr * Nn + gc])       = lo;
                *reinterpret_cast<float2*>(&Cf[(size_t)(gr + 8) * Nn + gc]) = hi;
            } else {
                uint32_t h01, l01, h23, l23;
                pack_hl(v0, v1, h01, l01);
                pack_hl(v2, v3, h23, l23);
                *reinterpret_cast<uint32_t*>(&Ch[(size_t)gr * Nn + gc])       = h01;
                *reinterpret_cast<uint32_t*>(&Cl[(size_t)gr * Nn + gc])       = l01;
                *reinterpret_cast<uint32_t*>(&Ch[(size_t)(gr + 8) * Nn + gc]) = h23;
                *reinterpret_cast<uint32_t*>(&Cl[(size_t)(gr + 8) * Nn + gc]) = l23;
            }
        }
    }
}

// ----------------------------------------------------------------------------
// Weight fp32 -> bf16 hi/lo split
// ----------------------------------------------------------------------------
__global__ void cvt_hl_k(const float* __restrict__ src, __nv_bfloat16* __restrict__ h,
                         __nv_bfloat16* __restrict__ l, int n) {
    int i = blockIdx.x * blockDim.x + threadIdx.x;
    if (i >= n) return;
    float v = src[i];
    __nv_bfloat16 hh = __float2bfloat16_rn(v);
    h[i] = hh;
    l[i] = __float2bfloat16_rn(v - __bfloat162float(hh));
}

// ----------------------------------------------------------------------------
// Input transpose: x (b, C, L) -> bf16 hi/lo t (b*L, C)
// ----------------------------------------------------------------------------
__global__ void transpose_in_k(const float* __restrict__ x, __nv_bfloat16* __restrict__ th,
                               __nv_bfloat16* __restrict__ tl, int Cc) {
    __shared__ float tile[32][33];
    int b  = blockIdx.z;
    int l0 = blockIdx.x * 32;
    int c0 = blockIdx.y * 32;
    int tx = threadIdx.x, ty = threadIdx.y;
    #pragma unroll
    for (int i = 0; i < 32; i += 8)
        tile[ty + i][tx] = x[((size_t)b * Cc + c0 + ty + i) * LL + l0 + tx];
    __syncthreads();
    #pragma unroll
    for (int i = 0; i < 32; i += 8) {
        float v = tile[tx][ty + i];
        __nv_bfloat16 hh = __float2bfloat16_rn(v);
        size_t idx = ((size_t)b * LL + l0 + ty + i) * Cc + c0 + tx;
        th[idx] = hh;
        tl[idx] = __float2bfloat16_rn(v - __bfloat162float(hh));
    }
}

__global__ void transpose_out_k(const float* __restrict__ t, float* __restrict__ o, int Cc) {
    __shared__ float tile[32][33];
    int b  = blockIdx.z;
    int l0 = blockIdx.x * 32;
    int c0 = blockIdx.y * 32;
    int tx = threadIdx.x, ty = threadIdx.y;
    #pragma unroll
    for (int i = 0; i < 32; i += 8)
        tile[ty + i][tx] = t[((size_t)b * LL + l0 + ty + i) * Cc + c0 + tx];
    __syncthreads();
    #pragma unroll
    for (int i = 0; i < 32; i += 8)
        o[((size_t)b * Cc + c0 + ty + i) * LL + l0 + tx] = tile[tx][ty + i];
}

// ----------------------------------------------------------------------------
// SIMT fp32 GEMM (thin xdbl projection only)
// ----------------------------------------------------------------------------
template <int BM, int BN, int BK, int TM, int TN, bool NGUARD>
__global__ __launch_bounds__((BM / TM) * (BN / TN))
void gemm_k(const float* __restrict__ A, const float* __restrict__ W,
            float* __restrict__ C, int Mm, int Nn, int Kk, int ldc) {
    constexpr int THREADS = (BM / TM) * (BN / TN);
    constexpr int KV = BK / 4;
    __shared__ float As[BK][BM];
    __shared__ float Bs[BK][BN];
    const int tid  = threadIdx.x;
    const int m0   = blockIdx.y * BM;
    const int n0   = blockIdx.x * BN;
    const int tcol = tid % (BN / TN);
    const int trow = tid / (BN / TN);
    float acc[TM][TN];
    #pragma unroll
    for (int i = 0; i < TM; i++)
        #pragma unroll
        for (int j = 0; j < TN; j++) acc[i][j] = 0.f;

    for (int k0 = 0; k0 < Kk; k0 += BK) {
        #pragma unroll
        for (int idx = tid; idx < BM * KV; idx += THREADS) {
            int am = idx / KV, ak = idx % KV;
            float4 v = *reinterpret_cast<const float4*>(A + (size_t)(m0 + am) * Kk + k0 + ak * 4);
            As[ak * 4 + 0][am] = v.x; As[ak * 4 + 1][am] = v.y;
            As[ak * 4 + 2][am] = v.z; As[ak * 4 + 3][am] = v.w;
        }
        #pragma unroll
        for (int idx = tid; idx < BN * KV; idx += THREADS) {
            int bn = idx / KV, bk = idx % KV;
            float4 v = make_float4(0.f, 0.f, 0.f, 0.f);
            if (!NGUARD || (n0 + bn) < Nn)
                v = *reinterpret_cast<const float4*>(W + (size_t)(n0 + bn) * Kk + k0 + bk * 4);
            Bs[bk * 4 + 0][bn] = v.x; Bs[bk * 4 + 1][bn] = v.y;
            Bs[bk * 4 + 2][bn] = v.z; Bs[bk * 4 + 3][bn] = v.w;
        }
        __syncthreads();
        #pragma unroll
        for (int k = 0; k < BK; k++) {
            float ra[TM], rb[TN];
            #pragma unroll
            for (int i = 0; i < TM; i++) ra[i] = As[k][trow * TM + i];
            #pragma unroll
            for (int j = 0; j < TN; j++) rb[j] = Bs[k][tcol * TN + j];
            #pragma unroll
            for (int i = 0; i < TM; i++)
                #pragma unroll
                for (int j = 0; j < TN; j++) acc[i][j] += ra[i] * rb[j];
        }
        __syncthreads();
    }

    #pragma unroll
    for (int i = 0; i < TM; i++) {
        int m = m0 + trow * TM + i;
        #pragma unroll
        for (int j = 0; j < TN; j++) {
            int n = n0 + tcol * TN + j;
            if (NGUARD && n >= Nn) continue;
            C[(size_t)m * ldc + n] = acc[i][j];
        }
    }
}

// ----------------------------------------------------------------------------
// Causal depthwise conv (k=4, pad (3,0)) + bias + silu.
// ----------------------------------------------------------------------------
__global__ void conv_silu_k(const float* __restrict__ xz, const float* __restrict__ cw,
                            const float* __restrict__ cb, float* __restrict__ out, int D) {
    int d = blockIdx.x * blockDim.x + threadIdx.x;
    int l = blockIdx.y, b = blockIdx.z;
    if (d >= D) return;
    int ld = 2 * D;
    size_t rowb = (size_t)b * LL + l;
    float w0 = cw[d * 4], w1 = cw[d * 4 + 1], w2 = cw[d * 4 + 2], w3 = cw[d * 4 + 3];
    float acc = cb[d];
    if (l >= 3) acc += xz[(rowb - 3) * ld + d] * w0;
    if (l >= 2) acc += xz[(rowb - 2) * ld + d] * w1;
    if (l >= 1) acc += xz[(rowb - 1) * ld + d] * w2;
    acc += xz[rowb * ld + d] * w3;
    out[rowb * D + d] = silu_f(acc);
}

// ----------------------------------------------------------------------------
// Chunked parallel scan.
// Phase A: chunk-local recurrence, storing ONLY chunk-final (h0, h1, S).
// ----------------------------------------------------------------------------
template <int R>
__global__ void scanA_k(const float* __restrict__ dbc, const float* __restrict__ conv,
                        const float* __restrict__ wdt, const float* __restrict__ bdt,
                        const float* __restrict__ alog,
                        float* __restrict__ chF, float* __restrict__ chS, int D) {
    __shared__ float sh[CHUNK * LDDBC];
    int d = threadIdx.x, ch = blockIdx.x, b = blockIdx.y;
    size_t lbase = (size_t)b * LL + ch * CHUNK;
    for (int idx = d; idx < CHUNK * LDDBC; idx += D)
        sh[idx] = dbc[lbase * LDDBC + idx];
    float wr[R];
    #pragma unroll
    for (int q = 0; q < R; q++) wr[q] = wdt[d * R + q];
    float A0 = -expf(alog[d * 2 + 0]);
    float A1 = -expf(alog[d * 2 + 1]);
    float bd = bdt[d];
    float h0 = 0.f, h1 = 0.f, S = 0.f;
    __syncthreads();
    for (int t0 = 0; t0 < CHUNK; t0 += 8) {
        float xcv[8];
        #pragma unroll
        for (int i = 0; i < 8; i++) xcv[i] = conv[(lbase + t0 + i) * D + d];
        #pragma unroll
        for (int i = 0; i < 8; i++) {
            const float* row = &sh[(t0 + i) * LDDBC];
            float dtr = bd;
            #pragma unroll
            for (int q = 0; q < R; q++) dtr += wr[q] * row[q];
            float dt = softplus_f(dtr);
            S += dt;
            float u = dt * xcv[i];
            h0 = expf(dt * A0) * h0 + u * row[R];
            h1 = expf(dt * A1) * h1 + u * row[R + 1];
        }
    }
    size_t ci = ((size_t)(b * NCH + ch)) * D + d;
    chF[ci * 2 + 0] = h0;
    chF[ci * 2 + 1] = h1;
    chS[ci] = S;
}

// Phase B: sequential prefix over chunk summaries.
__global__ void scanB_k(const float* __restrict__ chF, const float* __restrict__ chS,
                        const float* __restrict__ alog, float* __restrict__ hinit, int D) {
    int idx = blockIdx.x * blockDim.x + threadIdx.x;
    if (idx >= BB * D * 2) return;
    int j = idx & 1;
    int d = (idx >> 1) % D;
    int b = idx / (2 * D);
    float A = -expf(alog[d * 2 + j]);
    float H = 0.f;
    for (int ch = 0; ch < NCH; ch++) {
        size_t ci = ((size_t)(b * NCH + ch)) * D + d;
        hinit[ci * 2 + j] = H;
        H = expf(A * chS[ci]) * H + chF[ci * 2 + j];
    }
}

// Phase C: re-run recurrence seeded with h_init; write y as bf16 hi/lo.
template <int R>
__global__ void scanC_k(const float* __restrict__ dbc, const float* __restrict__ conv,
                        const float* __restrict__ xz, const float* __restrict__ hinit,
                        const float* __restrict__ wdt, const float* __restrict__ bdt,
                        const float* __restrict__ alog, const float* __restrict__ dd,
                        __nv_bfloat16* __restrict__ yh, __nv_bfloat16* __restrict__ yl,
                        int D) {
    __shared__ float sh[CHUNK * LDDBC];
    int d = threadIdx.x, ch = blockIdx.x, b = blockIdx.y;
    size_t lbase = (size_t)b * LL + ch * CHUNK;
    for (int idx = d; idx < CHUNK * LDDBC; idx += D)
        sh[idx] = dbc[lbase * LDDBC + idx];
    float wr[R];
    #pragma unroll
    for (int q = 0; q < R; q++) wr[q] = wdt[d * R + q];
    float A0 = -expf(alog[d * 2 + 0]);
    float A1 = -expf(alog[d * 2 + 1]);
    float bd = bdt[d];
    size_t ci = ((size_t)(b * NCH + ch)) * D + d;
    float h0 = hinit[ci * 2 + 0], h1 = hinit[ci * 2 + 1];
    float ddv = dd[d];
    int ld2 = 2 * D;
    __syncthreads();
    for (int t0 = 0; t0 < CHUNK; t0 += 8) {
        float xcv[8], zv[8];
        #pragma unroll
        for (int i = 0; i < 8; i++) {
            size_t rb = lbase + t0 + i;
            xcv[i] = conv[rb * D + d];
            zv[i]  = xz[rb * ld2 + D + d];
        }
        #pragma unroll
        for (int i = 0; i < 8; i++) {
            const float* row = &sh[(t0 + i) * LDDBC];
            float dtr = bd;
            #pragma unroll
            for (int q = 0; q < R; q++) dtr += wr[q] * row[q];
            float dt = softplus_f(dtr);
            float u = dt * xcv[i];
            h0 = expf(dt * A0) * h0 + u * row[R];
            h1 = expf(dt * A1) * h1 + u * row[R + 1];
            float y = h0 * row[R + 2] + h1 * row[R + 3] + ddv * xcv[i];
            y *= silu_f(zv[i]);
            __nv_bfloat16 hh = __float2bfloat16_rn(y);
            size_t oi = (lbase + t0 + i) * D + d;
            yh[oi] = hh;
            yl[oi] = __float2bfloat16_rn(y - __bfloat162float(hh));
        }
    }
}

// ----------------------------------------------------------------------------
// LayerNorm over last dim; output fp32 and/or bf16 hi/lo
// ----------------------------------------------------------------------------
__global__ void ln_k(const float* __restrict__ in, const float* __restrict__ w,
                     const float* __restrict__ bgm, float* __restrict__ outf,
                     __nv_bfloat16* __restrict__ outh, __nv_bfloat16* __restrict__ outl,
                     int D) {
    int m = blockIdx.x, d = threadIdx.x;
    float v = in[(size_t)m * D + d];
    float s = v, sq = v * v;
    #pragma unroll
    for (int o = 16; o > 0; o >>= 1) {
        s  += __shfl_xor_sync(0xffffffffu, s,  o);
        sq += __shfl_xor_sync(0xffffffffu, sq, o);
    }
    __shared__ float ws[8], wq[8];
    __shared__ float mu_s, rstd_s;
    int warp = d >> 5, lane = d & 31, nw = D >> 5;
    if (lane == 0) { ws[warp] = s; wq[warp] = sq; }
    __syncthreads();
    if (d == 0) {
        float ts = 0.f, tq = 0.f;
        for (int i = 0; i < nw; i++) { ts += ws[i]; tq += wq[i]; }
        float mu  = ts / D;
        float var = tq / D - mu * mu;
        mu_s = mu;
        rstd_s = rsqrtf(var + LN_EPS);
    }
    __syncthreads();
    float o = (v - mu_s) * rstd_s * w[d] + bgm[d];
    size_t oi = (size_t)m * D + d;
    if (outf) outf[oi] = o;
    if (outh) {
        __nv_bfloat16 hh = __float2bfloat16_rn(o);
        outh[oi] = hh;
        outl[oi] = __float2bfloat16_rn(o - __bfloat162float(hh));
    }
}

// ----------------------------------------------------------------------------
// Host-side driver
// ----------------------------------------------------------------------------
struct Bufs {
    float *XZ, *Conv, *DBC, *MO, *LN, *chF, *chS, *hin;
    __nv_bfloat16 *Ah, *Al, *LNh, *LNl, *Yh, *Yl, *Wh, *Wl;
};

static void mma_gemm(const __nv_bfloat16* Ah, const __nv_bfloat16* Al,
                     const __nv_bfloat16* Wh, const __nv_bfloat16* Wl,
                     const float* bias, float* Cf, __nv_bfloat16* Ch, __nv_bfloat16* Cl,
                     int N, int K, int epi) {
    mma_gemm_k<<<dim3(N / 128, MM / 128), 256, GSM_TOTAL>>>(
        Ah, Al, Wh, Wl, bias, Cf, Ch, Cl, N, K, epi);
}

static void run_stage(const float* const* p, const __nv_bfloat16* inH,
                      const __nv_bfloat16* inL, const __nv_bfloat16* winH,
                      const __nv_bfloat16* winL, const __nv_bfloat16* woutH,
                      const __nv_bfloat16* woutL, int D, int R, const Bufs& bf,
                      bool lastStage) {
    // 1. xz = X @ win^T + b_in
    mma_gemm(inH, inL, winH, winL, p[1], bf.XZ, nullptr, nullptr, 2 * D, D, 0);
    // 2. conv + silu
    conv_silu_k<<<dim3(D / 128, LL, BB), 128>>>(bf.XZ, p[2], p[3], bf.Conv, D);
    // 3. xdbl = xc @ wx^T (thin; SIMT fp32)
    gemm_k<128, 32, 16, 8, 2, true>
        <<<dim3(1, MM / 128), 256>>>(bf.Conv, p[4], bf.DBC, MM, R + 4, D, LDDBC);
    // 4-6. chunked scan
    if (R == 9) {
        scanA_k<9><<<dim3(NCH, BB), D>>>(bf.DBC, bf.Conv, p[5], p[6], p[7], bf.chF, bf.chS, D);
        scanB_k<<<(BB * D * 2 + 255) / 256, 256>>>(bf.chF, bf.chS, p[7], bf.hin, D);
        scanC_k<9><<<dim3(NCH, BB), D>>>(bf.DBC, bf.Conv, bf.XZ, bf.hin, p[5], p[6], p[7],
                                         p[8], bf.Yh, bf.Yl, D);
    } else {
        scanA_k<17><<<dim3(NCH, BB), D>>>(bf.DBC, bf.Conv, p[5], p[6], p[7], bf.chF, bf.chS, D);
        scanB_k<<<(BB * D * 2 + 255) / 256, 256>>>(bf.chF, bf.chS, p[7], bf.hin, D);
        scanC_k<17><<<dim3(NCH, BB), D>>>(bf.DBC, bf.Conv, bf.XZ, bf.hin, p[5], p[6], p[7],
                                          p[8], bf.Yh, bf.Yl, D);
    }
    // 7. out = y @ wout^T
    mma_gemm(bf.Yh, bf.Yl, woutH, woutL, nullptr, bf.MO, nullptr, nullptr, D, D, 0);
    // 8. layernorm (s1: bf16 hi/lo out for lin GEMM; s2: fp32 for transpose_out)
    if (!lastStage)
        ln_k<<<MM, D>>>(bf.MO, p[10], p[11], nullptr, bf.LNh, bf.LNl, D);
    else
        ln_k<<<MM, D>>>(bf.MO, p[10], p[11], bf.LN, nullptr, nullptr, D);
}

extern "C" void kernel_launch(void* const* d_in, const int* in_sizes, int n_in,
                              void* d_out, int out_size) {
    const float* x     = (const float*)d_in[0];
    const float* lin_w = (const float*)d_in[1];
    const float* lin_b = (const float*)d_in[2];
    const float* p1[12];
    const float* p2[12];
    for (int i = 0; i < 12; i++) p1[i] = (const float*)d_in[3 + i];
    for (int i = 0; i < 12; i++) p2[i] = (const float*)d_in[15 + i];
    float* out = (float*)d_out;

    cudaFuncSetAttribute(mma_gemm_k, cudaFuncAttributeMaxDynamicSharedMemorySize, GSM_TOTAL);

    Bufs bf;
    void* p;
    cudaGetSymbolAddress(&p, g_bufXZ);   bf.XZ   = (float*)p;
    cudaGetSymbolAddress(&p, g_bufConv); bf.Conv = (float*)p;
    cudaGetSymbolAddress(&p, g_bufDBC);  bf.DBC  = (float*)p;
    cudaGetSymbolAddress(&p, g_bufMO);   bf.MO   = (float*)p;
    cudaGetSymbolAddress(&p, g_bufLN);   bf.LN   = (float*)p;
    cudaGetSymbolAddress(&p, g_chunkF);  bf.chF  = (float*)p;
    cudaGetSymbolAddress(&p, g_chunkS);  bf.chS  = (float*)p;
    cudaGetSymbolAddress(&p, g_hinit);   bf.hin  = (float*)p;
    cudaGetSymbolAddress(&p, g_Ah);      bf.Ah   = (__nv_bfloat16*)p;
    cudaGetSymbolAddress(&p, g_Al);      bf.Al   = (__nv_bfloat16*)p;
    cudaGetSymbolAddress(&p, g_LNh);     bf.LNh  = (__nv_bfloat16*)p;
    cudaGetSymbolAddress(&p, g_LNl);     bf.LNl  = (__nv_bfloat16*)p;
    cudaGetSymbolAddress(&p, g_Yh);      bf.Yh   = (__nv_bfloat16*)p;
    cudaGetSymbolAddress(&p, g_Yl);      bf.Yl   = (__nv_bfloat16*)p;
    cudaGetSymbolAddress(&p, g_Wh);      bf.Wh   = (__nv_bfloat16*)p;
    cudaGetSymbolAddress(&p, g_Wl);      bf.Wl   = (__nv_bfloat16*)p;

    // Weight hi/lo conversion (once per launch; tiny)
    const int woWin1  = 0;            // 2*128*128 = 32768
    const int woWout1 = 32768;        // 128*128   = 16384
    const int woLin   = 49152;        // 256*128   = 32768
    const int woWin2  = 81920;        // 512*256   = 131072
    const int woWout2 = 212992;       // 256*256   = 65536
    cvt_hl_k<<<(32768 + 255) / 256, 256>>>(p1[0],  bf.Wh + woWin1,  bf.Wl + woWin1,  32768);
    cvt_hl_k<<<(16384 + 255) / 256, 256>>>(p1[9],  bf.Wh + woWout1, bf.Wl + woWout1, 16384);
    cvt_hl_k<<<(32768 + 255) / 256, 256>>>(lin_w,  bf.Wh + woLin,   bf.Wl + woLin,   32768);
    cvt_hl_k<<<(131072 + 255) / 256, 256>>>(p2[0], bf.Wh + woWin2,  bf.Wl + woWin2,  131072);
    cvt_hl_k<<<(65536 + 255) / 256, 256>>>(p2[9],  bf.Wh + woWout2, bf.Wl + woWout2, 65536);

    // Input transpose: x (8,128,4096) -> bf16 hi/lo (32768,128)
    transpose_in_k<<<dim3(LL / 32, 128 / 32, BB), dim3(32, 8)>>>(x, bf.Ah, bf.Al, 128);

    // Stage 1 (d=128, r=9)
    run_stage(p1, bf.Ah, bf.Al, bf.Wh + woWin1, bf.Wl + woWin1,
              bf.Wh + woWout1, bf.Wl + woWout1, 128, 9, bf, false);

    // Inter-stage linear + silu -> bf16 hi/lo activations for stage 2
    mma_gemm(bf.LNh, bf.LNl, bf.Wh + woLin, bf.Wl + woLin, lin_b,
             nullptr, bf.Ah, bf.Al, 256, 128, 1);

    // Stage 2 (d=256, r=17)
    run_stage(p2, bf.Ah, bf.Al, bf.Wh + woWin2, bf.Wl + woWin2,
              bf.Wh + woWout2, bf.Wl + woWout2, 256, 17, bf, true);

    // Output transpose: t (32768,256) -> out (8,256,4096)
    transpose_out_k<<<dim3(LL / 32, 256 / 32, BB), dim3(32, 8)>>>(bf.LN, out, 256);
}